// round 1
// baseline (speedup 1.0000x reference)
#include <cuda_runtime.h>

#define NB 4
#define NC 256
#define NH 128
#define NW 128
#define NPIX 16384
#define NHEADS 8
#define NCH 32
#define NSPLIT 32
#define GTILE 64

// ---------------- scratch (static device memory; no allocations) ----------------
__device__ float g_q[NB * NC * NPIX];                       // 64 MB
__device__ float g_k[NB * NC * NPIX];                       // 64 MB
__device__ float g_v[NB * NC * NPIX];                       // 64 MB
__device__ float g_partial[NSPLIT * NB * NHEADS * NCH * NCH]; // 4 MB
__device__ float g_attn[NB * NHEADS * NCH * NCH];           // 128 KB
__device__ float g_weff[NC * NC];
__device__ float g_beff[NC];
__device__ float g_afull[NB * NC * 2 * NC];                 // 2 MB

// ---------------- kernel 1: depthwise 3x3 conv -> q, k, v ----------------
__global__ __launch_bounds__(256) void dwconv_qkv(
    const float* __restrict__ x,
    const float* __restrict__ qw, const float* __restrict__ qb,
    const float* __restrict__ kw, const float* __restrict__ kb,
    const float* __restrict__ vw, const float* __restrict__ vb)
{
    int bc = blockIdx.x;            // 0..1023 = b*C + c
    int c  = bc & (NC - 1);
    const float* xp = x + (size_t)bc * NPIX;

    float wq[9], wk[9], wv[9];
#pragma unroll
    for (int t = 0; t < 9; t++) {
        wq[t] = qw[c * 9 + t];
        wk[t] = kw[c * 9 + t];
        wv[t] = vw[c * 9 + t];
    }
    float bq = qb[c], bk = kb[c], bv = vb[c];

    for (int idx = threadIdx.x; idx < NPIX; idx += 256) {
        int i = idx >> 7;
        int j = idx & 127;
        float aq = bq, ak = bk, av = bv;
#pragma unroll
        for (int dy = -1; dy <= 1; dy++) {
            int ii = i + dy;
            if (ii < 0 || ii >= NH) continue;
#pragma unroll
            for (int dx = -1; dx <= 1; dx++) {
                int jj = j + dx;
                if (jj < 0 || jj >= NW) continue;
                float xv = __ldg(xp + ii * NW + jj);
                int t = (dy + 1) * 3 + (dx + 1);
                aq = fmaf(wq[t], xv, aq);
                ak = fmaf(wk[t], xv, ak);
                av = fmaf(wv[t], xv, av);
            }
        }
        size_t o = (size_t)bc * NPIX + idx;
        g_q[o] = aq;
        g_k[o] = ak;
        g_v[o] = av;
    }
}

// ---------------- kernel 2: per-(b,h) gram matrix S = Q K^T, split over N ----------------
// grid: (bh=32, sp=32), 64 threads. Each thread owns a 4x4 tile of the 32x32 output.
__global__ __launch_bounds__(64) void gram_kernel()
{
    __shared__ __align__(16) float qs[GTILE][36]; // pad 36 to limit bank conflicts, keep 16B align
    __shared__ __align__(16) float ks[GTILE][36];

    int bh = blockIdx.x;            // 0..31
    int sp = blockIdx.y;            // 0..31
    const int nlen = NPIX / NSPLIT; // 512
    int n0 = sp * nlen;

    const float* qp = g_q + (size_t)bh * NCH * NPIX;
    const float* kp = g_k + (size_t)bh * NCH * NPIX;

    int tid = threadIdx.x;
    int tr = tid >> 3;   // 0..7 -> rows tr*4..tr*4+3
    int tc = tid & 7;    // 0..7 -> cols tc*4..tc*4+3

    float acc[4][4] = {};

    for (int t0 = n0; t0 < n0 + nlen; t0 += GTILE) {
        for (int l = tid; l < GTILE * NCH; l += 64) {
            int cc = l >> 6;     // channel 0..31
            int nn = l & 63;     // n within tile
            qs[nn][cc] = qp[(size_t)cc * NPIX + t0 + nn];
            ks[nn][cc] = kp[(size_t)cc * NPIX + t0 + nn];
        }
        __syncthreads();
#pragma unroll 4
        for (int nn = 0; nn < GTILE; nn++) {
            float4 qa = *(const float4*)&qs[nn][tr * 4];
            float4 kb = *(const float4*)&ks[nn][tc * 4];
            float qv[4] = {qa.x, qa.y, qa.z, qa.w};
            float kv[4] = {kb.x, kb.y, kb.z, kb.w};
#pragma unroll
            for (int i = 0; i < 4; i++)
#pragma unroll
                for (int j = 0; j < 4; j++)
                    acc[i][j] = fmaf(qv[i], kv[j], acc[i][j]);
        }
        __syncthreads();
    }

    float* pp = g_partial + ((size_t)sp * NB * NHEADS + bh) * NCH * NCH;
#pragma unroll
    for (int i = 0; i < 4; i++)
#pragma unroll
        for (int j = 0; j < 4; j++)
            pp[(tr * 4 + i) * NCH + (tc * 4 + j)] = acc[i][j];
}

// ---------------- kernel 3: reduce partials + temperature + softmax ----------------
// grid: 32 blocks (bh), 32 threads (row c)
__global__ __launch_bounds__(32) void softmax_kernel(const float* __restrict__ temperature)
{
    int bh = blockIdx.x;
    int h = bh & (NHEADS - 1);
    int c = threadIdx.x;
    float t = temperature[h];

    float vals[NCH];
#pragma unroll
    for (int d = 0; d < NCH; d++) {
        float s = 0.f;
        for (int sp = 0; sp < NSPLIT; sp++)
            s += g_partial[(((size_t)sp * NB * NHEADS + bh) * NCH + c) * NCH + d];
        vals[d] = s * t;
    }
    float mx = vals[0];
#pragma unroll
    for (int d = 1; d < NCH; d++) mx = fmaxf(mx, vals[d]);
    float sum = 0.f;
#pragma unroll
    for (int d = 0; d < NCH; d++) { vals[d] = __expf(vals[d] - mx); sum += vals[d]; }
    float inv = 1.f / sum;
    float* row = g_attn + ((size_t)bh * NCH + c) * NCH;
#pragma unroll
    for (int d = 0; d < NCH; d++) row[d] = vals[d] * inv;
}

// ---------------- kernel P1: W_eff = gamma * fusion_w[:, :256] @ out_w ; b_eff ----------------
__global__ __launch_bounds__(256) void weff_kernel(
    const float* __restrict__ fusion_w, const float* __restrict__ out_w,
    const float* __restrict__ out_b, const float* __restrict__ fusion_b,
    const float* __restrict__ gamma)
{
    int f = blockIdx.x;
    int c = threadIdx.x;
    float g = gamma[0];
    float s = 0.f;
    for (int o = 0; o < NC; o++)
        s = fmaf(fusion_w[f * 2 * NC + o], out_w[o * NC + c], s);
    g_weff[f * NC + c] = g * s;
    if (c == 0) {
        float sb = 0.f;
        for (int o = 0; o < NC; o++)
            sb = fmaf(fusion_w[f * 2 * NC + o], out_b[o], sb);
        g_beff[f] = g * sb + fusion_b[f];
    }
}

// ---------------- kernel P2: A_full[b][f][0:256] = W_eff (per-head) @ attn ; [256:512]=fusion_w tail ----------------
__global__ __launch_bounds__(512) void afull_kernel(const float* __restrict__ fusion_w)
{
    int bf = blockIdx.x;            // b*256 + f
    int b = bf >> 8, f = bf & 255;
    int col = threadIdx.x;          // 0..511
    float v;
    if (col < NC) {
        int h = col >> 5, d = col & 31;
        const float* wrow = g_weff + f * NC + h * NCH;
        const float* arow = g_attn + ((size_t)(b * NHEADS + h) * NCH) * NCH + d;
        float s = 0.f;
#pragma unroll
        for (int cc = 0; cc < NCH; cc++)
            s = fmaf(wrow[cc], arow[cc * NCH], s);
        v = s;
    } else {
        v = fusion_w[f * 2 * NC + col];
    }
    g_afull[(size_t)bf * 2 * NC + col] = v;
}

// ---------------- kernel 4: Y[b] = A_full[b](256x512) @ [v; x](512x16384) + b_eff ----------------
// BM=64, BN=128, BK=16, 128 threads, each thread 8x8
__global__ __launch_bounds__(128) void main_gemm(const float* __restrict__ x, float* __restrict__ y)
{
    __shared__ __align__(16) float As[16][64];   // [k][m]
    __shared__ __align__(16) float Bs[16][128];  // [k][n]

    int b  = blockIdx.z;
    int m0 = blockIdx.y * 64;
    int n0 = blockIdx.x * 128;
    int tid = threadIdx.x;
    int tx = tid & 15;    // n groups of 8
    int ty = tid >> 4;    // m groups of 8

    float acc[8][8] = {};
    const float* Ab = g_afull + ((size_t)b * NC + m0) * (2 * NC);

    for (int k0 = 0; k0 < 2 * NC; k0 += 16) {
        // load A tile: 64 rows x 16 cols = 256 float4, 2 per thread (store transposed)
#pragma unroll
        for (int r = 0; r < 2; r++) {
            int f4 = tid * 2 + r;       // 0..255
            int row = f4 >> 2;          // 0..63
            int cg  = f4 & 3;           // 0..3
            float4 a = *(const float4*)(Ab + (size_t)row * (2 * NC) + k0 + cg * 4);
            As[cg * 4 + 0][row] = a.x;
            As[cg * 4 + 1][row] = a.y;
            As[cg * 4 + 2][row] = a.z;
            As[cg * 4 + 3][row] = a.w;
        }
        // load B tile: 16 rows x 128 cols = 512 float4, 4 per thread
#pragma unroll
        for (int r = 0; r < 4; r++) {
            int id = tid + r * 128;     // 0..511
            int kk = id >> 5;           // 0..15
            int nc = (id & 31) * 4;     // 0..124
            int rowk = k0 + kk;
            const float* src = (rowk < NC)
                ? (g_v + (size_t)(b * NC + rowk) * NPIX)
                : (x   + (size_t)(b * NC + (rowk - NC)) * NPIX);
            *(float4*)&Bs[kk][nc] = *(const float4*)(src + n0 + nc);
        }
        __syncthreads();
#pragma unroll
        for (int k = 0; k < 16; k++) {
            float a[8], bv[8];
            *(float4*)(a)      = *(const float4*)&As[k][ty * 8];
            *(float4*)(a + 4)  = *(const float4*)&As[k][ty * 8 + 4];
            *(float4*)(bv)     = *(const float4*)&Bs[k][tx * 8];
            *(float4*)(bv + 4) = *(const float4*)&Bs[k][tx * 8 + 4];
#pragma unroll
            for (int i = 0; i < 8; i++)
#pragma unroll
                for (int j = 0; j < 8; j++)
                    acc[i][j] = fmaf(a[i], bv[j], acc[i][j]);
        }
        __syncthreads();
    }

#pragma unroll
    for (int i = 0; i < 8; i++) {
        int m = m0 + ty * 8 + i;
        float be = g_beff[m];
        float* yp = y + (size_t)(b * NC + m) * NPIX + n0 + tx * 8;
        float4 o0 = make_float4(acc[i][0] + be, acc[i][1] + be, acc[i][2] + be, acc[i][3] + be);
        float4 o1 = make_float4(acc[i][4] + be, acc[i][5] + be, acc[i][6] + be, acc[i][7] + be);
        *(float4*)(yp)     = o0;
        *(float4*)(yp + 4) = o1;
    }
}

// ---------------- launch ----------------
extern "C" void kernel_launch(void* const* d_in, const int* in_sizes, int n_in,
                              void* d_out, int out_size)
{
    const float* x        = (const float*)d_in[0];
    const float* q_w      = (const float*)d_in[1];
    const float* q_b      = (const float*)d_in[2];
    const float* k_w      = (const float*)d_in[3];
    const float* k_b      = (const float*)d_in[4];
    const float* v_w      = (const float*)d_in[5];
    const float* v_b      = (const float*)d_in[6];
    const float* out_w    = (const float*)d_in[7];
    const float* out_b    = (const float*)d_in[8];
    const float* fusion_w = (const float*)d_in[9];
    const float* fusion_b = (const float*)d_in[10];
    const float* temperature = (const float*)d_in[11];
    const float* gamma    = (const float*)d_in[12];
    float* y = (float*)d_out;

    dwconv_qkv<<<NB * NC, 256>>>(x, q_w, q_b, k_w, k_b, v_w, v_b);

    dim3 ggrid(NB * NHEADS, NSPLIT);
    gram_kernel<<<ggrid, 64>>>();

    softmax_kernel<<<NB * NHEADS, NCH>>>(temperature);

    weff_kernel<<<NC, NC>>>(fusion_w, out_w, out_b, fusion_b, gamma);
    afull_kernel<<<NB * NC, 2 * NC>>>(fusion_w);

    dim3 mgrid(NPIX / 128, NC / 64, NB);
    main_gemm<<<mgrid, 128>>>(x, y);
}

// round 2
// speedup vs baseline: 1.0581x; 1.0581x over previous
#include <cuda_runtime.h>

#define NB 4
#define NC 256
#define NH 128
#define NW 128
#define NPIX 16384
#define NHEADS 8
#define NCH 32
#define NSPLIT 32
#define GTILE 64

typedef unsigned long long ull;

__device__ __forceinline__ ull fpack(float lo, float hi) {
    ull r; asm("mov.b64 %0, {%1, %2};" : "=l"(r) : "f"(lo), "f"(hi)); return r;
}
__device__ __forceinline__ void ffma2(ull& d, ull a, ull b) {
    asm("fma.rn.f32x2 %0, %1, %2, %3;" : "=l"(d) : "l"(a), "l"(b), "l"(d));
}
__device__ __forceinline__ float2 funpack(ull v) {
    float2 r; asm("mov.b64 {%0, %1}, %2;" : "=f"(r.x), "=f"(r.y) : "l"(v)); return r;
}

// ---------------- scratch (static device memory; no allocations) ----------------
__device__ float g_q[NB * NC * NPIX];
__device__ float g_k[NB * NC * NPIX];
__device__ float g_v[NB * NC * NPIX];
__device__ float g_partial[NSPLIT * NB * NHEADS * NCH * NCH];
__device__ float g_attn[NB * NHEADS * NCH * NCH];
__device__ float g_weff[NC * NC];
__device__ float g_beff[NC];
__device__ float g_afull[NB * NC * 2 * NC];

// ---------------- kernel 1: depthwise 3x3 conv -> q, k, v (4 px / thread) ----------------
__global__ __launch_bounds__(256) void dwconv_qkv(
    const float* __restrict__ x,
    const float* __restrict__ qw, const float* __restrict__ qb,
    const float* __restrict__ kw, const float* __restrict__ kb,
    const float* __restrict__ vw, const float* __restrict__ vb)
{
    int bc = blockIdx.x;
    int c  = bc & (NC - 1);
    const float* xp = x + (size_t)bc * NPIX;

    float wq[9], wk[9], wv[9];
#pragma unroll
    for (int t = 0; t < 9; t++) {
        wq[t] = qw[c * 9 + t];
        wk[t] = kw[c * 9 + t];
        wv[t] = vw[c * 9 + t];
    }
    float bq = qb[c], bk = kb[c], bv = vb[c];

    for (int p = threadIdx.x; p < NPIX / 4; p += 256) {
        int i  = p >> 5;
        int j0 = (p & 31) * 4;
        float l[3][6];
#pragma unroll
        for (int dy = 0; dy < 3; dy++) {
            int ii = i + dy - 1;
            if (ii < 0 || ii >= NH) {
#pragma unroll
                for (int t = 0; t < 6; t++) l[dy][t] = 0.f;
            } else {
                const float* rp = xp + ii * NW;
                l[dy][0] = (j0 > 0) ? __ldg(rp + j0 - 1) : 0.f;
                float4 m = *(const float4*)(rp + j0);
                l[dy][1] = m.x; l[dy][2] = m.y; l[dy][3] = m.z; l[dy][4] = m.w;
                l[dy][5] = (j0 + 4 < NW) ? __ldg(rp + j0 + 4) : 0.f;
            }
        }
        float oq[4], ok[4], ov[4];
#pragma unroll
        for (int e = 0; e < 4; e++) {
            float aq = bq, ak = bk, av = bv;
#pragma unroll
            for (int dy = 0; dy < 3; dy++)
#pragma unroll
                for (int dx = 0; dx < 3; dx++) {
                    float xv = l[dy][e + dx];
                    int t = dy * 3 + dx;
                    aq = fmaf(wq[t], xv, aq);
                    ak = fmaf(wk[t], xv, ak);
                    av = fmaf(wv[t], xv, av);
                }
            oq[e] = aq; ok[e] = ak; ov[e] = av;
        }
        size_t o = (size_t)bc * NPIX + (size_t)p * 4;
        *(float4*)(g_q + o) = make_float4(oq[0], oq[1], oq[2], oq[3]);
        *(float4*)(g_k + o) = make_float4(ok[0], ok[1], ok[2], ok[3]);
        *(float4*)(g_v + o) = make_float4(ov[0], ov[1], ov[2], ov[3]);
    }
}

// ---------------- kernel 2: per-(b,h) gram matrix S = Q K^T, split over N ----------------
__global__ __launch_bounds__(64) void gram_kernel()
{
    __shared__ __align__(16) float qs[GTILE][36];
    __shared__ __align__(16) float ks[GTILE][36];

    int bh = blockIdx.x;
    int sp = blockIdx.y;
    const int nlen = NPIX / NSPLIT;
    int n0 = sp * nlen;

    const float* qp = g_q + (size_t)bh * NCH * NPIX;
    const float* kp = g_k + (size_t)bh * NCH * NPIX;

    int tid = threadIdx.x;
    int tr = tid >> 3;
    int tc = tid & 7;

    float acc[4][4] = {};

    for (int t0 = n0; t0 < n0 + nlen; t0 += GTILE) {
        for (int l = tid; l < GTILE * NCH; l += 64) {
            int cc = l >> 6;
            int nn = l & 63;
            qs[nn][cc] = qp[(size_t)cc * NPIX + t0 + nn];
            ks[nn][cc] = kp[(size_t)cc * NPIX + t0 + nn];
        }
        __syncthreads();
#pragma unroll 4
        for (int nn = 0; nn < GTILE; nn++) {
            float4 qa = *(const float4*)&qs[nn][tr * 4];
            float4 kb = *(const float4*)&ks[nn][tc * 4];
            float qv[4] = {qa.x, qa.y, qa.z, qa.w};
            float kv[4] = {kb.x, kb.y, kb.z, kb.w};
#pragma unroll
            for (int i = 0; i < 4; i++)
#pragma unroll
                for (int j = 0; j < 4; j++)
                    acc[i][j] = fmaf(qv[i], kv[j], acc[i][j]);
        }
        __syncthreads();
    }

    float* pp = g_partial + ((size_t)sp * NB * NHEADS + bh) * NCH * NCH;
#pragma unroll
    for (int i = 0; i < 4; i++)
#pragma unroll
        for (int j = 0; j < 4; j++)
            pp[(tr * 4 + i) * NCH + (tc * 4 + j)] = acc[i][j];
}

// ---------------- kernel 3: reduce partials + temperature + softmax ----------------
__global__ __launch_bounds__(32) void softmax_kernel(const float* __restrict__ temperature)
{
    int bh = blockIdx.x;
    int h = bh & (NHEADS - 1);
    int c = threadIdx.x;
    float t = temperature[h];

    float vals[NCH];
#pragma unroll
    for (int d = 0; d < NCH; d++) {
        float s = 0.f;
        for (int sp = 0; sp < NSPLIT; sp++)
            s += g_partial[(((size_t)sp * NB * NHEADS + bh) * NCH + c) * NCH + d];
        vals[d] = s * t;
    }
    float mx = vals[0];
#pragma unroll
    for (int d = 1; d < NCH; d++) mx = fmaxf(mx, vals[d]);
    float sum = 0.f;
#pragma unroll
    for (int d = 0; d < NCH; d++) { vals[d] = __expf(vals[d] - mx); sum += vals[d]; }
    float inv = 1.f / sum;
    float* row = g_attn + ((size_t)bh * NCH + c) * NCH;
#pragma unroll
    for (int d = 0; d < NCH; d++) row[d] = vals[d] * inv;
}

// ---------------- kernel P1: W_eff = gamma * fusion_w[:, :256] @ out_w  (tiled) ----------------
__global__ __launch_bounds__(256) void weff_kernel(
    const float* __restrict__ fusion_w, const float* __restrict__ out_w,
    const float* __restrict__ gamma)
{
    __shared__ float Fs[16][64];
    __shared__ float Os[16][68];

    int f0 = (blockIdx.x >> 2) * 64;
    int c0 = (blockIdx.x & 3) * 64;
    int tid = threadIdx.x;
    int tx = tid & 15, ty = tid >> 4;

    float acc[4][4] = {};

    for (int ko = 0; ko < NC; ko += 16) {
#pragma unroll
        for (int r = 0; r < 4; r++) {
            int id = tid + r * 256;
            int ff = id >> 4, kk = id & 15;
            Fs[kk][ff] = fusion_w[(f0 + ff) * (2 * NC) + ko + kk];
        }
#pragma unroll
        for (int r = 0; r < 4; r++) {
            int id = tid + r * 256;
            int kk = id >> 6, cc = id & 63;
            Os[kk][cc] = out_w[(ko + kk) * NC + c0 + cc];
        }
        __syncthreads();
#pragma unroll
        for (int k = 0; k < 16; k++) {
            float fv[4], ov[4];
#pragma unroll
            for (int i = 0; i < 4; i++) fv[i] = Fs[k][ty * 4 + i];
#pragma unroll
            for (int j = 0; j < 4; j++) ov[j] = Os[k][tx * 4 + j];
#pragma unroll
            for (int i = 0; i < 4; i++)
#pragma unroll
                for (int j = 0; j < 4; j++)
                    acc[i][j] = fmaf(fv[i], ov[j], acc[i][j]);
        }
        __syncthreads();
    }
    float g = gamma[0];
#pragma unroll
    for (int i = 0; i < 4; i++)
#pragma unroll
        for (int j = 0; j < 4; j++)
            g_weff[(f0 + ty * 4 + i) * NC + c0 + tx * 4 + j] = g * acc[i][j];
}

// ---------------- kernel P1b: b_eff ----------------
__global__ __launch_bounds__(32) void beff_kernel(
    const float* __restrict__ fusion_w, const float* __restrict__ out_b,
    const float* __restrict__ fusion_b, const float* __restrict__ gamma)
{
    int f = blockIdx.x;
    int l = threadIdx.x;
    float s = 0.f;
    for (int o = l; o < NC; o += 32)
        s = fmaf(fusion_w[f * 2 * NC + o], out_b[o], s);
#pragma unroll
    for (int off = 16; off; off >>= 1)
        s += __shfl_down_sync(0xffffffffu, s, off);
    if (l == 0) g_beff[f] = gamma[0] * s + fusion_b[f];
}

// ---------------- kernel P2: A_full ----------------
__global__ __launch_bounds__(512) void afull_kernel(const float* __restrict__ fusion_w)
{
    int bf = blockIdx.x;
    int b = bf >> 8, f = bf & 255;
    int col = threadIdx.x;
    float v;
    if (col < NC) {
        int h = col >> 5, d = col & 31;
        const float* wrow = g_weff + f * NC + h * NCH;
        const float* arow = g_attn + ((size_t)(b * NHEADS + h) * NCH) * NCH + d;
        float s = 0.f;
#pragma unroll
        for (int cc = 0; cc < NCH; cc++)
            s = fmaf(wrow[cc], arow[cc * NCH], s);
        v = s;
    } else {
        v = fusion_w[f * 2 * NC + col];
    }
    g_afull[(size_t)bf * 2 * NC + col] = v;
}

// ---------------- kernel 4: Y[b] = A_full[b](256x512) @ [v; x](512x16384) + b_eff ----------------
// BM=128, BN=128, BK=16, 256 threads, 8x8 per thread, packed f32x2 FFMA2.
__global__ __launch_bounds__(256, 2) void main_gemm(const float* __restrict__ x,
                                                    float* __restrict__ y)
{
    __shared__ __align__(16) ull   As[16][128];   // each entry = {a, a} duplicated pair
    __shared__ __align__(16) float Bs[16][128];

    int b  = blockIdx.z;
    int m0 = blockIdx.y * 128;
    int n0 = blockIdx.x * 128;
    int tid = threadIdx.x;
    int tx = tid & 15;   // n: 8 cols = 4 f32x2 pairs
    int ty = tid >> 4;   // m: 8 rows

    ull acc[8][4];
#pragma unroll
    for (int i = 0; i < 8; i++)
#pragma unroll
        for (int j = 0; j < 4; j++) acc[i][j] = 0ull;

    const float* Ab = g_afull + ((size_t)b * NC + m0) * (2 * NC);

    for (int k0 = 0; k0 < 2 * NC; k0 += 16) {
        // A tile: 128 rows x 16 k = 512 float4 -> 2 per thread, duplicated into pairs
#pragma unroll
        for (int r = 0; r < 2; r++) {
            int f4  = tid + r * 256;
            int row = f4 >> 2;
            int cg  = f4 & 3;
            float4 a = *(const float4*)(Ab + (size_t)row * (2 * NC) + k0 + cg * 4);
            As[cg * 4 + 0][row] = fpack(a.x, a.x);
            As[cg * 4 + 1][row] = fpack(a.y, a.y);
            As[cg * 4 + 2][row] = fpack(a.z, a.z);
            As[cg * 4 + 3][row] = fpack(a.w, a.w);
        }
        // B tile: 16 k x 128 n = 512 float4 -> 2 per thread
#pragma unroll
        for (int r = 0; r < 2; r++) {
            int id = tid + r * 256;
            int kk = id >> 5;
            int nc = (id & 31) * 4;
            int rowk = k0 + kk;
            const float* src = (rowk < NC)
                ? (g_v + (size_t)(b * NC + rowk) * NPIX)
                : (x   + (size_t)(b * NC + (rowk - NC)) * NPIX);
            *(float4*)&Bs[kk][nc] = *(const float4*)(src + n0 + nc);
        }
        __syncthreads();
#pragma unroll
        for (int k = 0; k < 16; k++) {
            ull bq[4];
#pragma unroll
            for (int j = 0; j < 4; j++)
                bq[j] = *(const ull*)&Bs[k][tx * 8 + j * 2];
#pragma unroll
            for (int i = 0; i < 8; i++) {
                ull ai = As[k][ty * 8 + i];
#pragma unroll
                for (int j = 0; j < 4; j++)
                    ffma2(acc[i][j], ai, bq[j]);
            }
        }
        __syncthreads();
    }

#pragma unroll
    for (int i = 0; i < 8; i++) {
        int m = m0 + ty * 8 + i;
        float be = g_beff[m];
        float o[8];
#pragma unroll
        for (int j = 0; j < 4; j++) {
            float2 t = funpack(acc[i][j]);
            o[j * 2]     = t.x + be;
            o[j * 2 + 1] = t.y + be;
        }
        float* yp = y + (size_t)(b * NC + m) * NPIX + n0 + tx * 8;
        *(float4*)(yp)     = make_float4(o[0], o[1], o[2], o[3]);
        *(float4*)(yp + 4) = make_float4(o[4], o[5], o[6], o[7]);
    }
}

// ---------------- launch ----------------
extern "C" void kernel_launch(void* const* d_in, const int* in_sizes, int n_in,
                              void* d_out, int out_size)
{
    const float* x        = (const float*)d_in[0];
    const float* q_w      = (const float*)d_in[1];
    const float* q_b      = (const float*)d_in[2];
    const float* k_w      = (const float*)d_in[3];
    const float* k_b      = (const float*)d_in[4];
    const float* v_w      = (const float*)d_in[5];
    const float* v_b      = (const float*)d_in[6];
    const float* out_w    = (const float*)d_in[7];
    const float* out_b    = (const float*)d_in[8];
    const float* fusion_w = (const float*)d_in[9];
    const float* fusion_b = (const float*)d_in[10];
    const float* temperature = (const float*)d_in[11];
    const float* gamma    = (const float*)d_in[12];
    float* y = (float*)d_out;

    dwconv_qkv<<<NB * NC, 256>>>(x, q_w, q_b, k_w, k_b, v_w, v_b);

    dim3 ggrid(NB * NHEADS, NSPLIT);
    gram_kernel<<<ggrid, 64>>>();

    softmax_kernel<<<NB * NHEADS, NCH>>>(temperature);

    weff_kernel<<<16, 256>>>(fusion_w, out_w, gamma);
    beff_kernel<<<NC, 32>>>(fusion_w, out_b, fusion_b, gamma);
    afull_kernel<<<NB * NC, 2 * NC>>>(fusion_w);

    dim3 mgrid(NPIX / 128, NC / 128, NB);
    main_gemm<<<mgrid, 256>>>(x, y);
}

// round 3
// speedup vs baseline: 1.3523x; 1.2781x over previous
#include <cuda_runtime.h>
#include <cuda_bf16.h>

#define NB 4
#define NC 256
#define NH 128
#define NW 128
#define NPIX 16384
#define NHEADS 8
#define NCH 32
#define NSPLIT 32
#define GTILE 64

// ---------------- scratch (static device memory; no allocations) ----------------
__device__ float g_q[NB * NC * NPIX];
__device__ float g_k[NB * NC * NPIX];
__device__ float g_v[NB * NC * NPIX];
__device__ float g_partial[NSPLIT * NB * NHEADS * NCH * NCH];
__device__ float g_attn[NB * NHEADS * NCH * NCH];
__device__ float g_weff[NC * NC];
__device__ float g_beff[NC];
__device__ float g_afull[NB * NC * 2 * NC];

// ---------------- kernel 1: depthwise 3x3 conv -> q, k, v (4 px / thread) ----------------
__global__ __launch_bounds__(256) void dwconv_qkv(
    const float* __restrict__ x,
    const float* __restrict__ qw, const float* __restrict__ qb,
    const float* __restrict__ kw, const float* __restrict__ kb,
    const float* __restrict__ vw, const float* __restrict__ vb)
{
    int bc = blockIdx.x;
    int c  = bc & (NC - 1);
    const float* xp = x + (size_t)bc * NPIX;

    float wq[9], wk[9], wv[9];
#pragma unroll
    for (int t = 0; t < 9; t++) {
        wq[t] = qw[c * 9 + t];
        wk[t] = kw[c * 9 + t];
        wv[t] = vw[c * 9 + t];
    }
    float bq = qb[c], bk = kb[c], bv = vb[c];

    for (int p = threadIdx.x; p < NPIX / 4; p += 256) {
        int i  = p >> 5;
        int j0 = (p & 31) * 4;
        float l[3][6];
#pragma unroll
        for (int dy = 0; dy < 3; dy++) {
            int ii = i + dy - 1;
            if (ii < 0 || ii >= NH) {
#pragma unroll
                for (int t = 0; t < 6; t++) l[dy][t] = 0.f;
            } else {
                const float* rp = xp + ii * NW;
                l[dy][0] = (j0 > 0) ? __ldg(rp + j0 - 1) : 0.f;
                float4 m = *(const float4*)(rp + j0);
                l[dy][1] = m.x; l[dy][2] = m.y; l[dy][3] = m.z; l[dy][4] = m.w;
                l[dy][5] = (j0 + 4 < NW) ? __ldg(rp + j0 + 4) : 0.f;
            }
        }
        float oq[4], ok[4], ov[4];
#pragma unroll
        for (int e = 0; e < 4; e++) {
            float aq = bq, ak = bk, av = bv;
#pragma unroll
            for (int dy = 0; dy < 3; dy++)
#pragma unroll
                for (int dx = 0; dx < 3; dx++) {
                    float xv = l[dy][e + dx];
                    int t = dy * 3 + dx;
                    aq = fmaf(wq[t], xv, aq);
                    ak = fmaf(wk[t], xv, ak);
                    av = fmaf(wv[t], xv, av);
                }
            oq[e] = aq; ok[e] = ak; ov[e] = av;
        }
        size_t o = (size_t)bc * NPIX + (size_t)p * 4;
        *(float4*)(g_q + o) = make_float4(oq[0], oq[1], oq[2], oq[3]);
        *(float4*)(g_k + o) = make_float4(ok[0], ok[1], ok[2], ok[3]);
        *(float4*)(g_v + o) = make_float4(ov[0], ov[1], ov[2], ov[3]);
    }
}

// ---------------- kernel 2: per-(b,h) gram matrix S = Q K^T, split over N ----------------
__global__ __launch_bounds__(64) void gram_kernel()
{
    __shared__ __align__(16) float qs[GTILE][36];
    __shared__ __align__(16) float ks[GTILE][36];

    int bh = blockIdx.x;
    int sp = blockIdx.y;
    const int nlen = NPIX / NSPLIT;
    int n0 = sp * nlen;

    const float* qp = g_q + (size_t)bh * NCH * NPIX;
    const float* kp = g_k + (size_t)bh * NCH * NPIX;

    int tid = threadIdx.x;
    int tr = tid >> 3;
    int tc = tid & 7;

    float acc[4][4] = {};

    for (int t0 = n0; t0 < n0 + nlen; t0 += GTILE) {
        for (int l = tid; l < GTILE * NCH; l += 64) {
            int cc = l >> 6;
            int nn = l & 63;
            qs[nn][cc] = qp[(size_t)cc * NPIX + t0 + nn];
            ks[nn][cc] = kp[(size_t)cc * NPIX + t0 + nn];
        }
        __syncthreads();
#pragma unroll 4
        for (int nn = 0; nn < GTILE; nn++) {
            float4 qa = *(const float4*)&qs[nn][tr * 4];
            float4 kb = *(const float4*)&ks[nn][tc * 4];
            float qv[4] = {qa.x, qa.y, qa.z, qa.w};
            float kv[4] = {kb.x, kb.y, kb.z, kb.w};
#pragma unroll
            for (int i = 0; i < 4; i++)
#pragma unroll
                for (int j = 0; j < 4; j++)
                    acc[i][j] = fmaf(qv[i], kv[j], acc[i][j]);
        }
        __syncthreads();
    }

    float* pp = g_partial + ((size_t)sp * NB * NHEADS + bh) * NCH * NCH;
#pragma unroll
    for (int i = 0; i < 4; i++)
#pragma unroll
        for (int j = 0; j < 4; j++)
            pp[(tr * 4 + i) * NCH + (tc * 4 + j)] = acc[i][j];
}

// ---------------- kernel 3: reduce partials + temperature + softmax ----------------
__global__ __launch_bounds__(32) void softmax_kernel(const float* __restrict__ temperature)
{
    int bh = blockIdx.x;
    int h = bh & (NHEADS - 1);
    int c = threadIdx.x;
    float t = temperature[h];

    float vals[NCH];
#pragma unroll
    for (int d = 0; d < NCH; d++) {
        float s = 0.f;
        for (int sp = 0; sp < NSPLIT; sp++)
            s += g_partial[(((size_t)sp * NB * NHEADS + bh) * NCH + c) * NCH + d];
        vals[d] = s * t;
    }
    float mx = vals[0];
#pragma unroll
    for (int d = 1; d < NCH; d++) mx = fmaxf(mx, vals[d]);
    float sum = 0.f;
#pragma unroll
    for (int d = 0; d < NCH; d++) { vals[d] = __expf(vals[d] - mx); sum += vals[d]; }
    float inv = 1.f / sum;
    float* row = g_attn + ((size_t)bh * NCH + c) * NCH;
#pragma unroll
    for (int d = 0; d < NCH; d++) row[d] = vals[d] * inv;
}

// ---------------- kernel P1: W_eff = gamma * fusion_w[:, :256] @ out_w  (tiled) ----------------
__global__ __launch_bounds__(256) void weff_kernel(
    const float* __restrict__ fusion_w, const float* __restrict__ out_w,
    const float* __restrict__ gamma)
{
    __shared__ float Fs[16][64];
    __shared__ float Os[16][68];

    int f0 = (blockIdx.x >> 2) * 64;
    int c0 = (blockIdx.x & 3) * 64;
    int tid = threadIdx.x;
    int tx = tid & 15, ty = tid >> 4;

    float acc[4][4] = {};

    for (int ko = 0; ko < NC; ko += 16) {
#pragma unroll
        for (int r = 0; r < 4; r++) {
            int id = tid + r * 256;
            int ff = id >> 4, kk = id & 15;
            Fs[kk][ff] = fusion_w[(f0 + ff) * (2 * NC) + ko + kk];
        }
#pragma unroll
        for (int r = 0; r < 4; r++) {
            int id = tid + r * 256;
            int kk = id >> 6, cc = id & 63;
            Os[kk][cc] = out_w[(ko + kk) * NC + c0 + cc];
        }
        __syncthreads();
#pragma unroll
        for (int k = 0; k < 16; k++) {
            float fv[4], ov[4];
#pragma unroll
            for (int i = 0; i < 4; i++) fv[i] = Fs[k][ty * 4 + i];
#pragma unroll
            for (int j = 0; j < 4; j++) ov[j] = Os[k][tx * 4 + j];
#pragma unroll
            for (int i = 0; i < 4; i++)
#pragma unroll
                for (int j = 0; j < 4; j++)
                    acc[i][j] = fmaf(fv[i], ov[j], acc[i][j]);
        }
        __syncthreads();
    }
    float g = gamma[0];
#pragma unroll
    for (int i = 0; i < 4; i++)
#pragma unroll
        for (int j = 0; j < 4; j++)
            g_weff[(f0 + ty * 4 + i) * NC + c0 + tx * 4 + j] = g * acc[i][j];
}

// ---------------- kernel P1b: b_eff ----------------
__global__ __launch_bounds__(32) void beff_kernel(
    const float* __restrict__ fusion_w, const float* __restrict__ out_b,
    const float* __restrict__ fusion_b, const float* __restrict__ gamma)
{
    int f = blockIdx.x;
    int l = threadIdx.x;
    float s = 0.f;
    for (int o = l; o < NC; o += 32)
        s = fmaf(fusion_w[f * 2 * NC + o], out_b[o], s);
#pragma unroll
    for (int off = 16; off; off >>= 1)
        s += __shfl_down_sync(0xffffffffu, s, off);
    if (l == 0) g_beff[f] = gamma[0] * s + fusion_b[f];
}

// ---------------- kernel P2: A_full ----------------
__global__ __launch_bounds__(512) void afull_kernel(const float* __restrict__ fusion_w)
{
    int bf = blockIdx.x;
    int b = bf >> 8, f = bf & 255;
    int col = threadIdx.x;
    float v;
    if (col < NC) {
        int h = col >> 5, d = col & 31;
        const float* wrow = g_weff + f * NC + h * NCH;
        const float* arow = g_attn + ((size_t)(b * NHEADS + h) * NCH) * NCH + d;
        float s = 0.f;
#pragma unroll
        for (int cc = 0; cc < NCH; cc++)
            s = fmaf(wrow[cc], arow[cc * NCH], s);
        v = s;
    } else {
        v = fusion_w[f * 2 * NC + col];
    }
    g_afull[(size_t)bf * 2 * NC + col] = v;
}

// ---------------- split helpers ----------------
__device__ __forceinline__ void split_bf16(float a, __nv_bfloat16& hi, __nv_bfloat16& lo) {
    hi = __float2bfloat16(a);
    lo = __float2bfloat16(a - __bfloat162float(hi));
}

__device__ __forceinline__ void mma_bf16(float* d, const unsigned* a, const unsigned* b) {
    asm volatile(
        "mma.sync.aligned.m16n8k16.row.col.f32.bf16.bf16.f32 "
        "{%0,%1,%2,%3}, {%4,%5,%6,%7}, {%8,%9}, {%0,%1,%2,%3};"
        : "+f"(d[0]), "+f"(d[1]), "+f"(d[2]), "+f"(d[3])
        : "r"(a[0]), "r"(a[1]), "r"(a[2]), "r"(a[3]), "r"(b[0]), "r"(b[1]));
}

// ---------------- kernel 4: Y[b] = A_full[b](256x512) @ [v; x](512x16384) + b_eff ----------------
// Tensor-core bf16, 3-product split (err ~2^-16). BM=256 (full M, B read once),
// BN=128, BK=16, 512 threads = 16 warps (4m x 4n), warp tile 64x32.
#define APITCH 24
__global__ __launch_bounds__(512, 1) void main_gemm(const float* __restrict__ x,
                                                    float* __restrict__ y)
{
    __shared__ __nv_bfloat16 Ah[256][APITCH];
    __shared__ __nv_bfloat16 Al[256][APITCH];
    __shared__ __nv_bfloat16 Bh[128][APITCH];
    __shared__ __nv_bfloat16 Bl[128][APITCH];

    int b  = blockIdx.y;
    int n0 = blockIdx.x * 128;
    int tid  = threadIdx.x;
    int lane = tid & 31;
    int warp = tid >> 5;
    int wm = (warp >> 2) * 64;   // m offset of warp tile
    int wn = (warp & 3) * 32;    // n offset of warp tile
    int g = lane >> 2;           // group row
    int t = lane & 3;

    const float* Ab = g_afull + (size_t)b * NC * 2 * NC;

    // B global load mapping: 16k x 128n = 512 float4; 1 per thread
    int bkk = tid >> 5;          // k row within tile (0..15)
    int bng = (tid & 31) * 4;    // n offset (0..124)
    // A global load mapping: 256m x 16k = 1024 float4; 2 per thread
    // id = tid + r*512: row = id>>2, kg = (id&3)*4

    float acc[4][4][4];
#pragma unroll
    for (int i = 0; i < 4; i++)
#pragma unroll
        for (int j = 0; j < 4; j++)
#pragma unroll
            for (int r = 0; r < 4; r++) acc[i][j][r] = 0.f;

    // prefetch B tile 0
    const float* bsrc0 = g_v + (size_t)(b * NC + bkk) * NPIX + n0 + bng;
    float4 pb = *(const float4*)bsrc0;

    for (int it = 0; it < 32; it++) {
        int k0 = it * 16;
        // issue A loads for this tile (latency overlaps the barrier below)
        float4 pa0, pa1;
        {
            int id0 = tid, id1 = tid + 512;
            pa0 = *(const float4*)(Ab + (size_t)(id0 >> 2) * (2 * NC) + k0 + (id0 & 3) * 4);
            pa1 = *(const float4*)(Ab + (size_t)(id1 >> 2) * (2 * NC) + k0 + (id1 & 3) * 4);
        }
        __syncthreads();  // previous compute done reading smem

        // store A (hi/lo), vectorized bf16x2
        {
            float av[2][4] = {{pa0.x, pa0.y, pa0.z, pa0.w}, {pa1.x, pa1.y, pa1.z, pa1.w}};
#pragma unroll
            for (int r = 0; r < 2; r++) {
                int id = tid + r * 512;
                int row = id >> 2, kg = (id & 3) * 4;
                __nv_bfloat16 h[4], l[4];
#pragma unroll
                for (int e = 0; e < 4; e++) split_bf16(av[r][e], h[e], l[e]);
                __nv_bfloat162 h01; h01.x = h[0]; h01.y = h[1];
                __nv_bfloat162 h23; h23.x = h[2]; h23.y = h[3];
                __nv_bfloat162 l01; l01.x = l[0]; l01.y = l[1];
                __nv_bfloat162 l23; l23.x = l[2]; l23.y = l[3];
                *(__nv_bfloat162*)&Ah[row][kg]     = h01;
                *(__nv_bfloat162*)&Ah[row][kg + 2] = h23;
                *(__nv_bfloat162*)&Al[row][kg]     = l01;
                *(__nv_bfloat162*)&Al[row][kg + 2] = l23;
            }
        }
        // store B transposed (hi/lo)
        {
            float bv[4] = {pb.x, pb.y, pb.z, pb.w};
#pragma unroll
            for (int e = 0; e < 4; e++) {
                __nv_bfloat16 h, l;
                split_bf16(bv[e], h, l);
                Bh[bng + e][bkk] = h;
                Bl[bng + e][bkk] = l;
            }
        }
        __syncthreads();  // smem tiles ready

        // prefetch next B tile (latency overlaps compute)
        if (it < 31) {
            int rowk = k0 + 16 + bkk;
            const float* src = (rowk < NC)
                ? (g_v + (size_t)(b * NC + rowk) * NPIX)
                : (x   + (size_t)(b * NC + (rowk - NC)) * NPIX);
            pb = *(const float4*)(src + n0 + bng);
        }

        // ---- compute: one k16 step ----
        unsigned ah[4][4], al[4][4];
#pragma unroll
        for (int mf = 0; mf < 4; mf++) {
            int m = wm + mf * 16 + g;
            ah[mf][0] = *(const unsigned*)&Ah[m][t * 2];
            ah[mf][1] = *(const unsigned*)&Ah[m + 8][t * 2];
            ah[mf][2] = *(const unsigned*)&Ah[m][t * 2 + 8];
            ah[mf][3] = *(const unsigned*)&Ah[m + 8][t * 2 + 8];
            al[mf][0] = *(const unsigned*)&Al[m][t * 2];
            al[mf][1] = *(const unsigned*)&Al[m + 8][t * 2];
            al[mf][2] = *(const unsigned*)&Al[m][t * 2 + 8];
            al[mf][3] = *(const unsigned*)&Al[m + 8][t * 2 + 8];
        }
#pragma unroll
        for (int nf = 0; nf < 4; nf++) {
            int n = wn + nf * 8 + g;
            unsigned bh[2], bl[2];
            bh[0] = *(const unsigned*)&Bh[n][t * 2];
            bh[1] = *(const unsigned*)&Bh[n][t * 2 + 8];
            bl[0] = *(const unsigned*)&Bl[n][t * 2];
            bl[1] = *(const unsigned*)&Bl[n][t * 2 + 8];
#pragma unroll
            for (int mf = 0; mf < 4; mf++) {
                mma_bf16(acc[mf][nf], ah[mf], bh);
                mma_bf16(acc[mf][nf], ah[mf], bl);
                mma_bf16(acc[mf][nf], al[mf], bh);
            }
        }
    }

    // epilogue: D layout c0:(g,2t) c1:(g,2t+1) c2:(g+8,2t) c3:(g+8,2t+1)
#pragma unroll
    for (int mf = 0; mf < 4; mf++) {
        int m = wm + mf * 16 + g;
        float be0 = g_beff[m];
        float be1 = g_beff[m + 8];
        float* yr0 = y + (size_t)(b * NC + m) * NPIX + n0 + wn;
        float* yr1 = yr0 + (size_t)8 * NPIX;
#pragma unroll
        for (int nf = 0; nf < 4; nf++) {
            float2 v0 = make_float2(acc[mf][nf][0] + be0, acc[mf][nf][1] + be0);
            float2 v1 = make_float2(acc[mf][nf][2] + be1, acc[mf][nf][3] + be1);
            *(float2*)(yr0 + nf * 8 + t * 2) = v0;
            *(float2*)(yr1 + nf * 8 + t * 2) = v1;
        }
    }
}

// ---------------- launch ----------------
extern "C" void kernel_launch(void* const* d_in, const int* in_sizes, int n_in,
                              void* d_out, int out_size)
{
    const float* x        = (const float*)d_in[0];
    const float* q_w      = (const float*)d_in[1];
    const float* q_b      = (const float*)d_in[2];
    const float* k_w      = (const float*)d_in[3];
    const float* k_b      = (const float*)d_in[4];
    const float* v_w      = (const float*)d_in[5];
    const float* v_b      = (const float*)d_in[6];
    const float* out_w    = (const float*)d_in[7];
    const float* out_b    = (const float*)d_in[8];
    const float* fusion_w = (const float*)d_in[9];
    const float* fusion_b = (const float*)d_in[10];
    const float* temperature = (const float*)d_in[11];
    const float* gamma    = (const float*)d_in[12];
    float* y = (float*)d_out;

    dwconv_qkv<<<NB * NC, 256>>>(x, q_w, q_b, k_w, k_b, v_w, v_b);

    dim3 ggrid(NB * NHEADS, NSPLIT);
    gram_kernel<<<ggrid, 64>>>();

    softmax_kernel<<<NB * NHEADS, NCH>>>(temperature);

    weff_kernel<<<16, 256>>>(fusion_w, out_w, gamma);
    beff_kernel<<<NC, 32>>>(fusion_w, out_b, fusion_b, gamma);
    afull_kernel<<<NB * NC, 2 * NC>>>(fusion_w);

    dim3 mgrid(NPIX / 128, NB);
    main_gemm<<<mgrid, 512>>>(x, y);
}

// round 4
// speedup vs baseline: 1.9962x; 1.4761x over previous
#include <cuda_runtime.h>
#include <cuda_bf16.h>

#define NB 4
#define NC 256
#define NH 128
#define NW 128
#define NPIX 16384
#define NHEADS 8
#define NCH 32
#define NSPLIT 32
#define GTILE 64

// ---------------- scratch (static device memory; no allocations) ----------------
__device__ float g_q[NB * NC * NPIX];
__device__ float g_k[NB * NC * NPIX];
__device__ __nv_bfloat16 g_vh[NB * NC * NPIX];
__device__ __nv_bfloat16 g_vl[NB * NC * NPIX];
__device__ __nv_bfloat16 g_xh[NB * NC * NPIX];
__device__ __nv_bfloat16 g_xl[NB * NC * NPIX];
__device__ float g_partial[NSPLIT * NB * NHEADS * NCH * NCH];
__device__ float g_attn[NB * NHEADS * NCH * NCH];
__device__ float g_weff[NC * NC];
__device__ float g_beff[NC];
__device__ __nv_bfloat16 g_ah[NB * NC * 2 * NC];
__device__ __nv_bfloat16 g_al[NB * NC * 2 * NC];

// ---------------- helpers ----------------
__device__ __forceinline__ void split_bf16(float a, __nv_bfloat16& hi, __nv_bfloat16& lo) {
    hi = __float2bfloat16(a);
    lo = __float2bfloat16(a - __bfloat162float(hi));
}
__device__ __forceinline__ unsigned pack_bf2(__nv_bfloat16 a, __nv_bfloat16 b) {
    __nv_bfloat162 t; t.x = a; t.y = b;
    return *(unsigned*)&t;
}
__device__ __forceinline__ void mma_bf16(float* d, const unsigned* a, const unsigned* b) {
    asm volatile(
        "mma.sync.aligned.m16n8k16.row.col.f32.bf16.bf16.f32 "
        "{%0,%1,%2,%3}, {%4,%5,%6,%7}, {%8,%9}, {%0,%1,%2,%3};"
        : "+f"(d[0]), "+f"(d[1]), "+f"(d[2]), "+f"(d[3])
        : "r"(a[0]), "r"(a[1]), "r"(a[2]), "r"(a[3]), "r"(b[0]), "r"(b[1]));
}
__device__ __forceinline__ void ldsm4(unsigned& d0, unsigned& d1, unsigned& d2, unsigned& d3,
                                      const void* p) {
    unsigned a = (unsigned)__cvta_generic_to_shared(p);
    asm volatile("ldmatrix.sync.aligned.m8n8.x4.shared.b16 {%0,%1,%2,%3},[%4];"
                 : "=r"(d0), "=r"(d1), "=r"(d2), "=r"(d3) : "r"(a));
}
__device__ __forceinline__ void ldsm4t(unsigned& d0, unsigned& d1, unsigned& d2, unsigned& d3,
                                       const void* p) {
    unsigned a = (unsigned)__cvta_generic_to_shared(p);
    asm volatile("ldmatrix.sync.aligned.m8n8.x4.trans.shared.b16 {%0,%1,%2,%3},[%4];"
                 : "=r"(d0), "=r"(d1), "=r"(d2), "=r"(d3) : "r"(a));
}
__device__ __forceinline__ void cpa16(void* s, const void* g) {
    unsigned sa = (unsigned)__cvta_generic_to_shared(s);
    asm volatile("cp.async.cg.shared.global [%0], [%1], 16;" :: "r"(sa), "l"(g));
}

// ---------------- kernel 1: dwconv 3x3 -> q,k fp32 ; v,x pre-split bf16 ----------------
__global__ __launch_bounds__(256) void dwconv_qkv(
    const float* __restrict__ x,
    const float* __restrict__ qw, const float* __restrict__ qb,
    const float* __restrict__ kw, const float* __restrict__ kb,
    const float* __restrict__ vw, const float* __restrict__ vb)
{
    int bc = blockIdx.x;
    int c  = bc & (NC - 1);
    const float* xp = x + (size_t)bc * NPIX;

    float wq[9], wk[9], wv[9];
#pragma unroll
    for (int t = 0; t < 9; t++) {
        wq[t] = qw[c * 9 + t];
        wk[t] = kw[c * 9 + t];
        wv[t] = vw[c * 9 + t];
    }
    float bq = qb[c], bk = kb[c], bv = vb[c];

    for (int p = threadIdx.x; p < NPIX / 4; p += 256) {
        int i  = p >> 5;
        int j0 = (p & 31) * 4;
        float l[3][6];
#pragma unroll
        for (int dy = 0; dy < 3; dy++) {
            int ii = i + dy - 1;
            if (ii < 0 || ii >= NH) {
#pragma unroll
                for (int t = 0; t < 6; t++) l[dy][t] = 0.f;
            } else {
                const float* rp = xp + ii * NW;
                l[dy][0] = (j0 > 0) ? __ldg(rp + j0 - 1) : 0.f;
                float4 m = *(const float4*)(rp + j0);
                l[dy][1] = m.x; l[dy][2] = m.y; l[dy][3] = m.z; l[dy][4] = m.w;
                l[dy][5] = (j0 + 4 < NW) ? __ldg(rp + j0 + 4) : 0.f;
            }
        }
        float oq[4], ok[4], ov[4];
#pragma unroll
        for (int e = 0; e < 4; e++) {
            float aq = bq, ak = bk, av = bv;
#pragma unroll
            for (int dy = 0; dy < 3; dy++)
#pragma unroll
                for (int dx = 0; dx < 3; dx++) {
                    float xv = l[dy][e + dx];
                    int t = dy * 3 + dx;
                    aq = fmaf(wq[t], xv, aq);
                    ak = fmaf(wk[t], xv, ak);
                    av = fmaf(wv[t], xv, av);
                }
            oq[e] = aq; ok[e] = ak; ov[e] = av;
        }
        size_t o = (size_t)bc * NPIX + (size_t)p * 4;
        *(float4*)(g_q + o) = make_float4(oq[0], oq[1], oq[2], oq[3]);
        *(float4*)(g_k + o) = make_float4(ok[0], ok[1], ok[2], ok[3]);

        __nv_bfloat16 h[4], lo[4];
#pragma unroll
        for (int e = 0; e < 4; e++) split_bf16(ov[e], h[e], lo[e]);
        *(uint2*)(g_vh + o) = make_uint2(pack_bf2(h[0], h[1]),  pack_bf2(h[2], h[3]));
        *(uint2*)(g_vl + o) = make_uint2(pack_bf2(lo[0], lo[1]), pack_bf2(lo[2], lo[3]));
#pragma unroll
        for (int e = 0; e < 4; e++) split_bf16(l[1][e + 1], h[e], lo[e]);
        *(uint2*)(g_xh + o) = make_uint2(pack_bf2(h[0], h[1]),  pack_bf2(h[2], h[3]));
        *(uint2*)(g_xl + o) = make_uint2(pack_bf2(lo[0], lo[1]), pack_bf2(lo[2], lo[3]));
    }
}

// ---------------- kernel 2: per-(b,h) gram matrix, split over N ----------------
__global__ __launch_bounds__(64) void gram_kernel()
{
    __shared__ __align__(16) float qs[GTILE][36];
    __shared__ __align__(16) float ks[GTILE][36];

    int bh = blockIdx.x;
    int sp = blockIdx.y;
    const int nlen = NPIX / NSPLIT;
    int n0 = sp * nlen;

    const float* qp = g_q + (size_t)bh * NCH * NPIX;
    const float* kp = g_k + (size_t)bh * NCH * NPIX;

    int tid = threadIdx.x;
    int tr = tid >> 3;
    int tc = tid & 7;

    float acc[4][4] = {};

    for (int t0 = n0; t0 < n0 + nlen; t0 += GTILE) {
        for (int l = tid; l < GTILE * NCH; l += 64) {
            int cc = l >> 6;
            int nn = l & 63;
            qs[nn][cc] = qp[(size_t)cc * NPIX + t0 + nn];
            ks[nn][cc] = kp[(size_t)cc * NPIX + t0 + nn];
        }
        __syncthreads();
#pragma unroll 4
        for (int nn = 0; nn < GTILE; nn++) {
            float4 qa = *(const float4*)&qs[nn][tr * 4];
            float4 kb = *(const float4*)&ks[nn][tc * 4];
            float qv[4] = {qa.x, qa.y, qa.z, qa.w};
            float kv[4] = {kb.x, kb.y, kb.z, kb.w};
#pragma unroll
            for (int i = 0; i < 4; i++)
#pragma unroll
                for (int j = 0; j < 4; j++)
                    acc[i][j] = fmaf(qv[i], kv[j], acc[i][j]);
        }
        __syncthreads();
    }

    float* pp = g_partial + ((size_t)sp * NB * NHEADS + bh) * NCH * NCH;
#pragma unroll
    for (int i = 0; i < 4; i++)
#pragma unroll
        for (int j = 0; j < 4; j++)
            pp[(tr * 4 + i) * NCH + (tc * 4 + j)] = acc[i][j];
}

// ---------------- kernel 3: reduce + softmax ----------------
__global__ __launch_bounds__(32) void softmax_kernel(const float* __restrict__ temperature)
{
    int bh = blockIdx.x;
    int h = bh & (NHEADS - 1);
    int c = threadIdx.x;
    float t = temperature[h];

    float vals[NCH];
#pragma unroll
    for (int d = 0; d < NCH; d++) {
        float s = 0.f;
        for (int sp = 0; sp < NSPLIT; sp++)
            s += g_partial[(((size_t)sp * NB * NHEADS + bh) * NCH + c) * NCH + d];
        vals[d] = s * t;
    }
    float mx = vals[0];
#pragma unroll
    for (int d = 1; d < NCH; d++) mx = fmaxf(mx, vals[d]);
    float sum = 0.f;
#pragma unroll
    for (int d = 0; d < NCH; d++) { vals[d] = __expf(vals[d] - mx); sum += vals[d]; }
    float inv = 1.f / sum;
    float* row = g_attn + ((size_t)bh * NCH + c) * NCH;
#pragma unroll
    for (int d = 0; d < NCH; d++) row[d] = vals[d] * inv;
}

// ---------------- kernel P1: W_eff ----------------
__global__ __launch_bounds__(256) void weff_kernel(
    const float* __restrict__ fusion_w, const float* __restrict__ out_w,
    const float* __restrict__ gamma)
{
    __shared__ float Fs[16][64];
    __shared__ float Os[16][68];

    int f0 = (blockIdx.x >> 2) * 64;
    int c0 = (blockIdx.x & 3) * 64;
    int tid = threadIdx.x;
    int tx = tid & 15, ty = tid >> 4;

    float acc[4][4] = {};

    for (int ko = 0; ko < NC; ko += 16) {
#pragma unroll
        for (int r = 0; r < 4; r++) {
            int id = tid + r * 256;
            int ff = id >> 4, kk = id & 15;
            Fs[kk][ff] = fusion_w[(f0 + ff) * (2 * NC) + ko + kk];
        }
#pragma unroll
        for (int r = 0; r < 4; r++) {
            int id = tid + r * 256;
            int kk = id >> 6, cc = id & 63;
            Os[kk][cc] = out_w[(ko + kk) * NC + c0 + cc];
        }
        __syncthreads();
#pragma unroll
        for (int k = 0; k < 16; k++) {
            float fv[4], ov[4];
#pragma unroll
            for (int i = 0; i < 4; i++) fv[i] = Fs[k][ty * 4 + i];
#pragma unroll
            for (int j = 0; j < 4; j++) ov[j] = Os[k][tx * 4 + j];
#pragma unroll
            for (int i = 0; i < 4; i++)
#pragma unroll
                for (int j = 0; j < 4; j++)
                    acc[i][j] = fmaf(fv[i], ov[j], acc[i][j]);
        }
        __syncthreads();
    }
    float g = gamma[0];
#pragma unroll
    for (int i = 0; i < 4; i++)
#pragma unroll
        for (int j = 0; j < 4; j++)
            g_weff[(f0 + ty * 4 + i) * NC + c0 + tx * 4 + j] = g * acc[i][j];
}

// ---------------- kernel P1b: b_eff ----------------
__global__ __launch_bounds__(32) void beff_kernel(
    const float* __restrict__ fusion_w, const float* __restrict__ out_b,
    const float* __restrict__ fusion_b, const float* __restrict__ gamma)
{
    int f = blockIdx.x;
    int l = threadIdx.x;
    float s = 0.f;
    for (int o = l; o < NC; o += 32)
        s = fmaf(fusion_w[f * 2 * NC + o], out_b[o], s);
#pragma unroll
    for (int off = 16; off; off >>= 1)
        s += __shfl_down_sync(0xffffffffu, s, off);
    if (l == 0) g_beff[f] = gamma[0] * s + fusion_b[f];
}

// ---------------- kernel P2: A_full -> pre-split bf16 ----------------
__global__ __launch_bounds__(512) void afull_kernel(const float* __restrict__ fusion_w)
{
    int bf = blockIdx.x;
    int b = bf >> 8, f = bf & 255;
    int col = threadIdx.x;
    float v;
    if (col < NC) {
        int h = col >> 5, d = col & 31;
        const float* wrow = g_weff + f * NC + h * NCH;
        const float* arow = g_attn + ((size_t)(b * NHEADS + h) * NCH) * NCH + d;
        float s = 0.f;
#pragma unroll
        for (int cc = 0; cc < NCH; cc++)
            s = fmaf(wrow[cc], arow[cc * NCH], s);
        v = s;
    } else {
        v = fusion_w[f * 2 * NC + col];
    }
    __nv_bfloat16 hi, lo;
    split_bf16(v, hi, lo);
    g_ah[(size_t)bf * 2 * NC + col] = hi;
    g_al[(size_t)bf * 2 * NC + col] = lo;
}

// ---------------- kernel 4: main GEMM — bf16 HMMA, cp.async 2-stage, ldmatrix ----------------
// Y[b](256x16384) = A(256x512) @ [v; x](512x16384) + b_eff
// BM=128, BN=128, BK=16, 256 threads = 8 warps (2m x 4n), warp tile 64x32.
#define AP 24     // A smem pitch (bf16) -> 48B rows, conflict-free ldmatrix
#define BP 136    // B smem pitch (bf16) -> 272B rows, conflict-free ldmatrix
__global__ __launch_bounds__(256, 2) void main_gemm(float* __restrict__ y)
{
    __shared__ __align__(128) __nv_bfloat16 As[2][2][128][AP];
    __shared__ __align__(128) __nv_bfloat16 Bs[2][2][16][BP];

    int b  = blockIdx.z;
    int m0 = blockIdx.y * 128;
    int n0 = blockIdx.x * 128;
    int tid  = threadIdx.x;
    int lane = tid & 31;
    int warp = tid >> 5;
    int wm = (warp >> 2) * 64;
    int wn = (warp & 3) * 32;
    int g = lane >> 2;
    int t = lane & 3;

    // ldmatrix lane addressing (same pattern for A and B)
    int lr = lane & 15;          // row within 16
    int lc = (lane >> 4) * 8;    // 8-col group

    // cp.async mappings
    // A: 512 chunks/stage: id: half=id>>8, row=(id&255)>>1, kc=(id&1)*8
    // B: 512 chunks/stage: id: half=id>>8, krow=(id&255)>>4, nc=((id&255)&15)*8
    const __nv_bfloat16* gA[2] = { g_ah + (size_t)(b * NC + m0) * (2 * NC),
                                   g_al + (size_t)(b * NC + m0) * (2 * NC) };

    float acc[4][4][4];
#pragma unroll
    for (int i = 0; i < 4; i++)
#pragma unroll
        for (int j = 0; j < 4; j++)
#pragma unroll
            for (int r = 0; r < 4; r++) acc[i][j][r] = 0.f;

    auto load_stage = [&](int s, int it) {
        int k0 = it * 16;
#pragma unroll
        for (int c = 0; c < 2; c++) {
            int id = tid + c * 256;
            int half = id >> 8;
            int rem = id & 255;
            int row = rem >> 1;
            int kc = (rem & 1) * 8;
            cpa16(&As[s][half][row][kc], gA[half] + (size_t)row * (2 * NC) + k0 + kc);
        }
#pragma unroll
        for (int c = 0; c < 2; c++) {
            int id = tid + c * 256;
            int half = id >> 8;
            int rem = id & 255;
            int krow = rem >> 4;
            int nc = (rem & 15) * 8;
            int grow = k0 + krow;
            const __nv_bfloat16* src;
            if (grow < NC)
                src = (half ? g_vl : g_vh) + (size_t)(b * NC + grow) * NPIX + n0 + nc;
            else
                src = (half ? g_xl : g_xh) + (size_t)(b * NC + grow - NC) * NPIX + n0 + nc;
            cpa16(&Bs[s][half][krow][nc], src);
        }
        asm volatile("cp.async.commit_group;");
    };

    load_stage(0, 0);

    for (int it = 0; it < 32; it++) {
        int cur = it & 1;
        if (it + 1 < 32) {
            load_stage(cur ^ 1, it + 1);
            asm volatile("cp.async.wait_group 1;");
        } else {
            asm volatile("cp.async.wait_group 0;");
        }
        __syncthreads();

        // B fragments (hi and lo)
        unsigned bh[4][2], bl[4][2];
#pragma unroll
        for (int nb = 0; nb < 2; nb++) {
            unsigned d0, d1, d2, d3;
            ldsm4t(d0, d1, d2, d3, &Bs[cur][0][lr][wn + nb * 16 + lc]);
            bh[nb * 2][0] = d0; bh[nb * 2][1] = d1;
            bh[nb * 2 + 1][0] = d2; bh[nb * 2 + 1][1] = d3;
            ldsm4t(d0, d1, d2, d3, &Bs[cur][1][lr][wn + nb * 16 + lc]);
            bl[nb * 2][0] = d0; bl[nb * 2][1] = d1;
            bl[nb * 2 + 1][0] = d2; bl[nb * 2 + 1][1] = d3;
        }
        // pass 1: Ah * (Bh + Bl)
        {
            unsigned ah[4][4];
#pragma unroll
            for (int mf = 0; mf < 4; mf++)
                ldsm4(ah[mf][0], ah[mf][1], ah[mf][2], ah[mf][3],
                      &As[cur][0][wm + mf * 16 + lr][lc]);
#pragma unroll
            for (int nf = 0; nf < 4; nf++)
#pragma unroll
                for (int mf = 0; mf < 4; mf++) {
                    mma_bf16(acc[mf][nf], ah[mf], bh[nf]);
                    mma_bf16(acc[mf][nf], ah[mf], bl[nf]);
                }
        }
        // pass 2: Al * Bh
        {
            unsigned al[4][4];
#pragma unroll
            for (int mf = 0; mf < 4; mf++)
                ldsm4(al[mf][0], al[mf][1], al[mf][2], al[mf][3],
                      &As[cur][1][wm + mf * 16 + lr][lc]);
#pragma unroll
            for (int nf = 0; nf < 4; nf++)
#pragma unroll
                for (int mf = 0; mf < 4; mf++)
                    mma_bf16(acc[mf][nf], al[mf], bh[nf]);
        }
        __syncthreads();
    }

    // epilogue
#pragma unroll
    for (int mf = 0; mf < 4; mf++) {
        int m = m0 + wm + mf * 16 + g;
        float be0 = g_beff[m];
        float be1 = g_beff[m + 8];
        float* yr0 = y + (size_t)(b * NC + m) * NPIX + n0 + wn;
        float* yr1 = yr0 + (size_t)8 * NPIX;
#pragma unroll
        for (int nf = 0; nf < 4; nf++) {
            *(float2*)(yr0 + nf * 8 + t * 2) =
                make_float2(acc[mf][nf][0] + be0, acc[mf][nf][1] + be0);
            *(float2*)(yr1 + nf * 8 + t * 2) =
                make_float2(acc[mf][nf][2] + be1, acc[mf][nf][3] + be1);
        }
    }
}

// ---------------- launch ----------------
extern "C" void kernel_launch(void* const* d_in, const int* in_sizes, int n_in,
                              void* d_out, int out_size)
{
    const float* x        = (const float*)d_in[0];
    const float* q_w      = (const float*)d_in[1];
    const float* q_b      = (const float*)d_in[2];
    const float* k_w      = (const float*)d_in[3];
    const float* k_b      = (const float*)d_in[4];
    const float* v_w      = (const float*)d_in[5];
    const float* v_b      = (const float*)d_in[6];
    const float* out_w    = (const float*)d_in[7];
    const float* out_b    = (const float*)d_in[8];
    const float* fusion_w = (const float*)d_in[9];
    const float* fusion_b = (const float*)d_in[10];
    const float* temperature = (const float*)d_in[11];
    const float* gamma    = (const float*)d_in[12];
    float* y = (float*)d_out;

    dwconv_qkv<<<NB * NC, 256>>>(x, q_w, q_b, k_w, k_b, v_w, v_b);

    dim3 ggrid(NB * NHEADS, NSPLIT);
    gram_kernel<<<ggrid, 64>>>();

    softmax_kernel<<<NB * NHEADS, NCH>>>(temperature);

    weff_kernel<<<16, 256>>>(fusion_w, out_w, gamma);
    beff_kernel<<<NC, 32>>>(fusion_w, out_b, fusion_b, gamma);
    afull_kernel<<<NB * NC, 2 * NC>>>(fusion_w);

    dim3 mgrid(NPIX / 128, NC / 128, NB);
    main_gemm<<<mgrid, 256>>>(y);
}

// round 5
// speedup vs baseline: 2.0167x; 1.0103x over previous
#include <cuda_runtime.h>
#include <cuda_bf16.h>

#define NB 4
#define NC 256
#define NH 128
#define NW 128
#define NPIX 16384
#define NHEADS 8
#define NCH 32
#define NSPLIT 32
#define GTILE 64

// ---------------- scratch (static device memory; no allocations) ----------------
__device__ float g_q[NB * NC * NPIX];
__device__ float g_k[NB * NC * NPIX];
__device__ __nv_bfloat16 g_vh[NB * NC * NPIX];
__device__ __nv_bfloat16 g_vl[NB * NC * NPIX];
__device__ __nv_bfloat16 g_xh[NB * NC * NPIX];
__device__ __nv_bfloat16 g_xl[NB * NC * NPIX];
__device__ float g_partial[NSPLIT * NB * NHEADS * NCH * NCH];
__device__ float g_attn[NB * NHEADS * NCH * NCH];
__device__ float g_weff[NC * NC];
__device__ float g_beff[NC];
__device__ __nv_bfloat16 g_ah[NB * NC * 2 * NC];
__device__ __nv_bfloat16 g_al[NB * NC * 2 * NC];

// ---------------- helpers ----------------
__device__ __forceinline__ void split_bf16(float a, __nv_bfloat16& hi, __nv_bfloat16& lo) {
    hi = __float2bfloat16(a);
    lo = __float2bfloat16(a - __bfloat162float(hi));
}
__device__ __forceinline__ unsigned pack_bf2(__nv_bfloat16 a, __nv_bfloat16 b) {
    __nv_bfloat162 t; t.x = a; t.y = b;
    return *(unsigned*)&t;
}
__device__ __forceinline__ void mma_bf16(float* d, const unsigned* a, const unsigned* b) {
    asm volatile(
        "mma.sync.aligned.m16n8k16.row.col.f32.bf16.bf16.f32 "
        "{%0,%1,%2,%3}, {%4,%5,%6,%7}, {%8,%9}, {%0,%1,%2,%3};"
        : "+f"(d[0]), "+f"(d[1]), "+f"(d[2]), "+f"(d[3])
        : "r"(a[0]), "r"(a[1]), "r"(a[2]), "r"(a[3]), "r"(b[0]), "r"(b[1]));
}
__device__ __forceinline__ void ldsm4(unsigned& d0, unsigned& d1, unsigned& d2, unsigned& d3,
                                      const void* p) {
    unsigned a = (unsigned)__cvta_generic_to_shared(p);
    asm volatile("ldmatrix.sync.aligned.m8n8.x4.shared.b16 {%0,%1,%2,%3},[%4];"
                 : "=r"(d0), "=r"(d1), "=r"(d2), "=r"(d3) : "r"(a));
}
__device__ __forceinline__ void ldsm4t(unsigned& d0, unsigned& d1, unsigned& d2, unsigned& d3,
                                       const void* p) {
    unsigned a = (unsigned)__cvta_generic_to_shared(p);
    asm volatile("ldmatrix.sync.aligned.m8n8.x4.trans.shared.b16 {%0,%1,%2,%3},[%4];"
                 : "=r"(d0), "=r"(d1), "=r"(d2), "=r"(d3) : "r"(a));
}
__device__ __forceinline__ void cpa16(void* s, const void* g) {
    unsigned sa = (unsigned)__cvta_generic_to_shared(s);
    asm volatile("cp.async.cg.shared.global [%0], [%1], 16;" :: "r"(sa), "l"(g));
}

// ---------------- kernel 1: dwconv 3x3 -> q,k fp32 ; v,x pre-split bf16 ----------------
__global__ __launch_bounds__(256) void dwconv_qkv(
    const float* __restrict__ x,
    const float* __restrict__ qw, const float* __restrict__ qb,
    const float* __restrict__ kw, const float* __restrict__ kb,
    const float* __restrict__ vw, const float* __restrict__ vb)
{
    int bc = blockIdx.x;
    int c  = bc & (NC - 1);
    const float* xp = x + (size_t)bc * NPIX;

    float wq[9], wk[9], wv[9];
#pragma unroll
    for (int t = 0; t < 9; t++) {
        wq[t] = qw[c * 9 + t];
        wk[t] = kw[c * 9 + t];
        wv[t] = vw[c * 9 + t];
    }
    float bq = qb[c], bk = kb[c], bv = vb[c];

    for (int p = threadIdx.x; p < NPIX / 4; p += 256) {
        int i  = p >> 5;
        int j0 = (p & 31) * 4;
        float l[3][6];
#pragma unroll
        for (int dy = 0; dy < 3; dy++) {
            int ii = i + dy - 1;
            if (ii < 0 || ii >= NH) {
#pragma unroll
                for (int t = 0; t < 6; t++) l[dy][t] = 0.f;
            } else {
                const float* rp = xp + ii * NW;
                l[dy][0] = (j0 > 0) ? __ldg(rp + j0 - 1) : 0.f;
                float4 m = *(const float4*)(rp + j0);
                l[dy][1] = m.x; l[dy][2] = m.y; l[dy][3] = m.z; l[dy][4] = m.w;
                l[dy][5] = (j0 + 4 < NW) ? __ldg(rp + j0 + 4) : 0.f;
            }
        }
        float oq[4], ok[4], ov[4];
#pragma unroll
        for (int e = 0; e < 4; e++) {
            float aq = bq, ak = bk, av = bv;
#pragma unroll
            for (int dy = 0; dy < 3; dy++)
#pragma unroll
                for (int dx = 0; dx < 3; dx++) {
                    float xv = l[dy][e + dx];
                    int t = dy * 3 + dx;
                    aq = fmaf(wq[t], xv, aq);
                    ak = fmaf(wk[t], xv, ak);
                    av = fmaf(wv[t], xv, av);
                }
            oq[e] = aq; ok[e] = ak; ov[e] = av;
        }
        size_t o = (size_t)bc * NPIX + (size_t)p * 4;
        *(float4*)(g_q + o) = make_float4(oq[0], oq[1], oq[2], oq[3]);
        *(float4*)(g_k + o) = make_float4(ok[0], ok[1], ok[2], ok[3]);

        __nv_bfloat16 h[4], lo[4];
#pragma unroll
        for (int e = 0; e < 4; e++) split_bf16(ov[e], h[e], lo[e]);
        *(uint2*)(g_vh + o) = make_uint2(pack_bf2(h[0], h[1]),  pack_bf2(h[2], h[3]));
        *(uint2*)(g_vl + o) = make_uint2(pack_bf2(lo[0], lo[1]), pack_bf2(lo[2], lo[3]));
#pragma unroll
        for (int e = 0; e < 4; e++) split_bf16(l[1][e + 1], h[e], lo[e]);
        *(uint2*)(g_xh + o) = make_uint2(pack_bf2(h[0], h[1]),  pack_bf2(h[2], h[3]));
        *(uint2*)(g_xl + o) = make_uint2(pack_bf2(lo[0], lo[1]), pack_bf2(lo[2], lo[3]));
    }
}

// ---------------- kernel 2: per-(b,h) gram matrix, split over N ----------------
__global__ __launch_bounds__(64) void gram_kernel()
{
    __shared__ __align__(16) float qs[GTILE][36];
    __shared__ __align__(16) float ks[GTILE][36];

    int bh = blockIdx.x;
    int sp = blockIdx.y;
    const int nlen = NPIX / NSPLIT;
    int n0 = sp * nlen;

    const float* qp = g_q + (size_t)bh * NCH * NPIX;
    const float* kp = g_k + (size_t)bh * NCH * NPIX;

    int tid = threadIdx.x;
    int tr = tid >> 3;
    int tc = tid & 7;

    float acc[4][4] = {};

    for (int t0 = n0; t0 < n0 + nlen; t0 += GTILE) {
        for (int l = tid; l < GTILE * NCH; l += 64) {
            int cc = l >> 6;
            int nn = l & 63;
            qs[nn][cc] = qp[(size_t)cc * NPIX + t0 + nn];
            ks[nn][cc] = kp[(size_t)cc * NPIX + t0 + nn];
        }
        __syncthreads();
#pragma unroll 4
        for (int nn = 0; nn < GTILE; nn++) {
            float4 qa = *(const float4*)&qs[nn][tr * 4];
            float4 kb = *(const float4*)&ks[nn][tc * 4];
            float qv[4] = {qa.x, qa.y, qa.z, qa.w};
            float kv[4] = {kb.x, kb.y, kb.z, kb.w};
#pragma unroll
            for (int i = 0; i < 4; i++)
#pragma unroll
                for (int j = 0; j < 4; j++)
                    acc[i][j] = fmaf(qv[i], kv[j], acc[i][j]);
        }
        __syncthreads();
    }

    float* pp = g_partial + ((size_t)sp * NB * NHEADS + bh) * NCH * NCH;
#pragma unroll
    for (int i = 0; i < 4; i++)
#pragma unroll
        for (int j = 0; j < 4; j++)
            pp[(tr * 4 + i) * NCH + (tc * 4 + j)] = acc[i][j];
}

// ---------------- kernel 3: reduce + softmax ----------------
__global__ __launch_bounds__(32) void softmax_kernel(const float* __restrict__ temperature)
{
    int bh = blockIdx.x;
    int h = bh & (NHEADS - 1);
    int c = threadIdx.x;
    float t = temperature[h];

    float vals[NCH];
#pragma unroll
    for (int d = 0; d < NCH; d++) {
        float s = 0.f;
        for (int sp = 0; sp < NSPLIT; sp++)
            s += g_partial[(((size_t)sp * NB * NHEADS + bh) * NCH + c) * NCH + d];
        vals[d] = s * t;
    }
    float mx = vals[0];
#pragma unroll
    for (int d = 1; d < NCH; d++) mx = fmaxf(mx, vals[d]);
    float sum = 0.f;
#pragma unroll
    for (int d = 0; d < NCH; d++) { vals[d] = __expf(vals[d] - mx); sum += vals[d]; }
    float inv = 1.f / sum;
    float* row = g_attn + ((size_t)bh * NCH + c) * NCH;
#pragma unroll
    for (int d = 0; d < NCH; d++) row[d] = vals[d] * inv;
}

// ---------------- kernel P1: W_eff (+ b_eff in warp 0 of last block row) ----------------
__global__ __launch_bounds__(256) void weff_kernel(
    const float* __restrict__ fusion_w, const float* __restrict__ out_w,
    const float* __restrict__ out_b, const float* __restrict__ fusion_b,
    const float* __restrict__ gamma)
{
    __shared__ float Fs[16][64];
    __shared__ float Os[16][68];

    int f0 = (blockIdx.x >> 2) * 64;
    int c0 = (blockIdx.x & 3) * 64;
    int tid = threadIdx.x;
    int tx = tid & 15, ty = tid >> 4;

    // b_eff: blocks with c0==0 compute 64 rows each using 64 threads
    if ((blockIdx.x & 3) == 0 && tid < 64) {
        int f = f0 + tid;
        float sb = 0.f;
        for (int o = 0; o < NC; o++)
            sb = fmaf(fusion_w[f * 2 * NC + o], out_b[o], sb);
        g_beff[f] = gamma[0] * sb + fusion_b[f];
    }

    float acc[4][4] = {};

    for (int ko = 0; ko < NC; ko += 16) {
#pragma unroll
        for (int r = 0; r < 4; r++) {
            int id = tid + r * 256;
            int ff = id >> 4, kk = id & 15;
            Fs[kk][ff] = fusion_w[(f0 + ff) * (2 * NC) + ko + kk];
        }
#pragma unroll
        for (int r = 0; r < 4; r++) {
            int id = tid + r * 256;
            int kk = id >> 6, cc = id & 63;
            Os[kk][cc] = out_w[(ko + kk) * NC + c0 + cc];
        }
        __syncthreads();
#pragma unroll
        for (int k = 0; k < 16; k++) {
            float fv[4], ov[4];
#pragma unroll
            for (int i = 0; i < 4; i++) fv[i] = Fs[k][ty * 4 + i];
#pragma unroll
            for (int j = 0; j < 4; j++) ov[j] = Os[k][tx * 4 + j];
#pragma unroll
            for (int i = 0; i < 4; i++)
#pragma unroll
                for (int j = 0; j < 4; j++)
                    acc[i][j] = fmaf(fv[i], ov[j], acc[i][j]);
        }
        __syncthreads();
    }
    float g = gamma[0];
#pragma unroll
    for (int i = 0; i < 4; i++)
#pragma unroll
        for (int j = 0; j < 4; j++)
            g_weff[(f0 + ty * 4 + i) * NC + c0 + tx * 4 + j] = g * acc[i][j];
}

// ---------------- kernel P2: A_full -> pre-split bf16 ----------------
__global__ __launch_bounds__(512) void afull_kernel(const float* __restrict__ fusion_w)
{
    int bf = blockIdx.x;
    int b = bf >> 8, f = bf & 255;
    int col = threadIdx.x;
    float v;
    if (col < NC) {
        int h = col >> 5, d = col & 31;
        const float* wrow = g_weff + f * NC + h * NCH;
        const float* arow = g_attn + ((size_t)(b * NHEADS + h) * NCH) * NCH + d;
        float s = 0.f;
#pragma unroll
        for (int cc = 0; cc < NCH; cc++)
            s = fmaf(wrow[cc], arow[cc * NCH], s);
        v = s;
    } else {
        v = fusion_w[f * 2 * NC + col];
    }
    __nv_bfloat16 hi, lo;
    split_bf16(v, hi, lo);
    g_ah[(size_t)bf * 2 * NC + col] = hi;
    g_al[(size_t)bf * 2 * NC + col] = lo;
}

// ---------------- kernel 4: main GEMM — bf16 HMMA, cp.async 2-stage, BK=32 ----------------
// Y[b](256x16384) = A(256x512) @ [v; x](512x16384) + b_eff
// BM=128, BN=128, BK=32, 256 threads = 8 warps (2m x 4n), warp tile 64x32.
#define AP 40     // A smem pitch (bf16): 80B rows -> conflict-free ldmatrix
#define BP 136    // B smem pitch (bf16): 272B rows -> conflict-free ldmatrix.trans
__global__ __launch_bounds__(256, 2) void main_gemm(float* __restrict__ y)
{
    __shared__ __align__(128) __nv_bfloat16 As[2][2][128][AP];
    __shared__ __align__(128) __nv_bfloat16 Bs[2][2][32][BP];

    int b  = blockIdx.z;
    int m0 = blockIdx.y * 128;
    int n0 = blockIdx.x * 128;
    int tid  = threadIdx.x;
    int lane = tid & 31;
    int warp = tid >> 5;
    int wm = (warp >> 2) * 64;
    int wn = (warp & 3) * 32;
    int g = lane >> 2;
    int t = lane & 3;

    int lr = lane & 15;          // ldmatrix row within 16
    int lc = (lane >> 4) * 8;    // ldmatrix 8-col group

    const __nv_bfloat16* gA[2] = { g_ah + (size_t)(b * NC + m0) * (2 * NC),
                                   g_al + (size_t)(b * NC + m0) * (2 * NC) };

    float acc[4][4][4];
#pragma unroll
    for (int i = 0; i < 4; i++)
#pragma unroll
        for (int j = 0; j < 4; j++)
#pragma unroll
            for (int r = 0; r < 4; r++) acc[i][j][r] = 0.f;

    auto load_stage = [&](int s, int it) {
        int k0 = it * 32;
        // A: 128 rows x 32 k x 2 halves = 1024 16B chunks, 4/thread
#pragma unroll
        for (int c = 0; c < 4; c++) {
            int id = tid + c * 256;
            int half = id >> 9;
            int rem = id & 511;
            int row = rem >> 2;
            int kc = (rem & 3) * 8;
            cpa16(&As[s][half][row][kc], gA[half] + (size_t)row * (2 * NC) + k0 + kc);
        }
        // B: 32 k x 128 n x 2 halves = 1024 chunks, 4/thread
#pragma unroll
        for (int c = 0; c < 4; c++) {
            int id = tid + c * 256;
            int half = id >> 9;
            int rem = id & 511;
            int krow = rem >> 4;
            int nc = (rem & 15) * 8;
            int grow = k0 + krow;
            const __nv_bfloat16* src;
            if (grow < NC)
                src = (half ? g_vl : g_vh) + (size_t)(b * NC + grow) * NPIX + n0 + nc;
            else
                src = (half ? g_xl : g_xh) + (size_t)(b * NC + grow - NC) * NPIX + n0 + nc;
            cpa16(&Bs[s][half][krow][nc], src);
        }
        asm volatile("cp.async.commit_group;");
    };

    load_stage(0, 0);

    const int NIT = (2 * NC) / 32;   // 16
    for (int it = 0; it < NIT; it++) {
        int cur = it & 1;
        if (it + 1 < NIT) {
            load_stage(cur ^ 1, it + 1);
            asm volatile("cp.async.wait_group 1;");
        } else {
            asm volatile("cp.async.wait_group 0;");
        }
        __syncthreads();

#pragma unroll
        for (int ks = 0; ks < 2; ks++) {
            int kof = ks * 16;
            // B fragments (hi and lo)
            unsigned bh[4][2], bl[4][2];
#pragma unroll
            for (int nb = 0; nb < 2; nb++) {
                unsigned d0, d1, d2, d3;
                ldsm4t(d0, d1, d2, d3, &Bs[cur][0][kof + lr][wn + nb * 16 + lc]);
                bh[nb * 2][0] = d0; bh[nb * 2][1] = d1;
                bh[nb * 2 + 1][0] = d2; bh[nb * 2 + 1][1] = d3;
                ldsm4t(d0, d1, d2, d3, &Bs[cur][1][kof + lr][wn + nb * 16 + lc]);
                bl[nb * 2][0] = d0; bl[nb * 2][1] = d1;
                bl[nb * 2 + 1][0] = d2; bl[nb * 2 + 1][1] = d3;
            }
            // pass 1: Ah * (Bh + Bl)
            {
                unsigned ah[4][4];
#pragma unroll
                for (int mf = 0; mf < 4; mf++)
                    ldsm4(ah[mf][0], ah[mf][1], ah[mf][2], ah[mf][3],
                          &As[cur][0][wm + mf * 16 + lr][kof + lc]);
#pragma unroll
                for (int nf = 0; nf < 4; nf++)
#pragma unroll
                    for (int mf = 0; mf < 4; mf++) {
                        mma_bf16(acc[mf][nf], ah[mf], bh[nf]);
                        mma_bf16(acc[mf][nf], ah[mf], bl[nf]);
                    }
            }
            // pass 2: Al * Bh
            {
                unsigned al[4][4];
#pragma unroll
                for (int mf = 0; mf < 4; mf++)
                    ldsm4(al[mf][0], al[mf][1], al[mf][2], al[mf][3],
                          &As[cur][1][wm + mf * 16 + lr][kof + lc]);
#pragma unroll
                for (int nf = 0; nf < 4; nf++)
#pragma unroll
                    for (int mf = 0; mf < 4; mf++)
                        mma_bf16(acc[mf][nf], al[mf], bh[nf]);
            }
        }
        __syncthreads();
    }

    // epilogue
#pragma unroll
    for (int mf = 0; mf < 4; mf++) {
        int m = m0 + wm + mf * 16 + g;
        float be0 = g_beff[m];
        float be1 = g_beff[m + 8];
        float* yr0 = y + (size_t)(b * NC + m) * NPIX + n0 + wn;
        float* yr1 = yr0 + (size_t)8 * NPIX;
#pragma unroll
        for (int nf = 0; nf < 4; nf++) {
            *(float2*)(yr0 + nf * 8 + t * 2) =
                make_float2(acc[mf][nf][0] + be0, acc[mf][nf][1] + be0);
            *(float2*)(yr1 + nf * 8 + t * 2) =
                make_float2(acc[mf][nf][2] + be1, acc[mf][nf][3] + be1);
        }
    }
}

// ---------------- launch ----------------
extern "C" void kernel_launch(void* const* d_in, const int* in_sizes, int n_in,
                              void* d_out, int out_size)
{
    const float* x        = (const float*)d_in[0];
    const float* q_w      = (const float*)d_in[1];
    const float* q_b      = (const float*)d_in[2];
    const float* k_w      = (const float*)d_in[3];
    const float* k_b      = (const float*)d_in[4];
    const float* v_w      = (const float*)d_in[5];
    const float* v_b      = (const float*)d_in[6];
    const float* out_w    = (const float*)d_in[7];
    const float* out_b    = (const float*)d_in[8];
    const float* fusion_w = (const float*)d_in[9];
    const float* fusion_b = (const float*)d_in[10];
    const float* temperature = (const float*)d_in[11];
    const float* gamma    = (const float*)d_in[12];
    float* y = (float*)d_out;

    dwconv_qkv<<<NB * NC, 256>>>(x, q_w, q_b, k_w, k_b, v_w, v_b);

    dim3 ggrid(NB * NHEADS, NSPLIT);
    gram_kernel<<<ggrid, 64>>>();

    softmax_kernel<<<NB * NHEADS, NCH>>>(temperature);

    weff_kernel<<<16, 256>>>(fusion_w, out_w, out_b, fusion_b, gamma);
    afull_kernel<<<NB * NC, 2 * NC>>>(fusion_w);

    dim3 mgrid(NPIX / 128, NC / 128, NB);
    main_gemm<<<mgrid, 256>>>(y);
}

// round 6
// speedup vs baseline: 2.0948x; 1.0387x over previous
#include <cuda_runtime.h>
#include <cuda_bf16.h>

#define NB 4
#define NC 256
#define NH 128
#define NW 128
#define NPIX 16384
#define NHEADS 8
#define NCH 32
#define NSPLIT 32
#define GTILE 64

// ---------------- scratch (static device memory; no allocations) ----------------
__device__ float g_q[NB * NC * NPIX];
__device__ float g_k[NB * NC * NPIX];
__device__ __nv_bfloat16 g_vh[NB * NC * NPIX];
__device__ __nv_bfloat16 g_vl[NB * NC * NPIX];
__device__ __nv_bfloat16 g_xh[NB * NC * NPIX];
__device__ __nv_bfloat16 g_xl[NB * NC * NPIX];
__device__ float g_partial[NSPLIT * NB * NHEADS * NCH * NCH];
__device__ float g_attn[NB * NHEADS * NCH * NCH];
__device__ float g_weff[NC * NC];
__device__ float g_beff[NC];
__device__ __nv_bfloat16 g_ah[NB * NC * 2 * NC];
__device__ __nv_bfloat16 g_al[NB * NC * 2 * NC];

// ---------------- helpers ----------------
__device__ __forceinline__ void split_bf16(float a, __nv_bfloat16& hi, __nv_bfloat16& lo) {
    hi = __float2bfloat16(a);
    lo = __float2bfloat16(a - __bfloat162float(hi));
}
__device__ __forceinline__ unsigned pack_bf2(__nv_bfloat16 a, __nv_bfloat16 b) {
    __nv_bfloat162 t; t.x = a; t.y = b;
    return *(unsigned*)&t;
}
__device__ __forceinline__ void mma_bf16(float* d, const unsigned* a, const unsigned* b) {
    asm volatile(
        "mma.sync.aligned.m16n8k16.row.col.f32.bf16.bf16.f32 "
        "{%0,%1,%2,%3}, {%4,%5,%6,%7}, {%8,%9}, {%0,%1,%2,%3};"
        : "+f"(d[0]), "+f"(d[1]), "+f"(d[2]), "+f"(d[3])
        : "r"(a[0]), "r"(a[1]), "r"(a[2]), "r"(a[3]), "r"(b[0]), "r"(b[1]));
}
__device__ __forceinline__ void ldsm4(unsigned& d0, unsigned& d1, unsigned& d2, unsigned& d3,
                                      const void* p) {
    unsigned a = (unsigned)__cvta_generic_to_shared(p);
    asm volatile("ldmatrix.sync.aligned.m8n8.x4.shared.b16 {%0,%1,%2,%3},[%4];"
                 : "=r"(d0), "=r"(d1), "=r"(d2), "=r"(d3) : "r"(a));
}
__device__ __forceinline__ void ldsm4t(unsigned& d0, unsigned& d1, unsigned& d2, unsigned& d3,
                                       const void* p) {
    unsigned a = (unsigned)__cvta_generic_to_shared(p);
    asm volatile("ldmatrix.sync.aligned.m8n8.x4.trans.shared.b16 {%0,%1,%2,%3},[%4];"
                 : "=r"(d0), "=r"(d1), "=r"(d2), "=r"(d3) : "r"(a));
}
__device__ __forceinline__ void cpa16(void* s, const void* g) {
    unsigned sa = (unsigned)__cvta_generic_to_shared(s);
    asm volatile("cp.async.cg.shared.global [%0], [%1], 16;" :: "r"(sa), "l"(g));
}

// ---------------- kernel 1: dwconv 3x3 -> q,k fp32 ; v,x pre-split bf16 ----------------
__global__ __launch_bounds__(256) void dwconv_qkv(
    const float* __restrict__ x,
    const float* __restrict__ qw, const float* __restrict__ qb,
    const float* __restrict__ kw, const float* __restrict__ kb,
    const float* __restrict__ vw, const float* __restrict__ vb)
{
    int bc = blockIdx.x;
    int c  = bc & (NC - 1);
    const float* xp = x + (size_t)bc * NPIX;

    float wq[9], wk[9], wv[9];
#pragma unroll
    for (int t = 0; t < 9; t++) {
        wq[t] = qw[c * 9 + t];
        wk[t] = kw[c * 9 + t];
        wv[t] = vw[c * 9 + t];
    }
    float bq = qb[c], bk = kb[c], bv = vb[c];

    for (int p = threadIdx.x; p < NPIX / 4; p += 256) {
        int i  = p >> 5;
        int j0 = (p & 31) * 4;
        float l[3][6];
#pragma unroll
        for (int dy = 0; dy < 3; dy++) {
            int ii = i + dy - 1;
            if (ii < 0 || ii >= NH) {
#pragma unroll
                for (int t = 0; t < 6; t++) l[dy][t] = 0.f;
            } else {
                const float* rp = xp + ii * NW;
                l[dy][0] = (j0 > 0) ? __ldg(rp + j0 - 1) : 0.f;
                float4 m = *(const float4*)(rp + j0);
                l[dy][1] = m.x; l[dy][2] = m.y; l[dy][3] = m.z; l[dy][4] = m.w;
                l[dy][5] = (j0 + 4 < NW) ? __ldg(rp + j0 + 4) : 0.f;
            }
        }
        float oq[4], ok[4], ov[4];
#pragma unroll
        for (int e = 0; e < 4; e++) {
            float aq = bq, ak = bk, av = bv;
#pragma unroll
            for (int dy = 0; dy < 3; dy++)
#pragma unroll
                for (int dx = 0; dx < 3; dx++) {
                    float xv = l[dy][e + dx];
                    int t = dy * 3 + dx;
                    aq = fmaf(wq[t], xv, aq);
                    ak = fmaf(wk[t], xv, ak);
                    av = fmaf(wv[t], xv, av);
                }
            oq[e] = aq; ok[e] = ak; ov[e] = av;
        }
        size_t o = (size_t)bc * NPIX + (size_t)p * 4;
        *(float4*)(g_q + o) = make_float4(oq[0], oq[1], oq[2], oq[3]);
        *(float4*)(g_k + o) = make_float4(ok[0], ok[1], ok[2], ok[3]);

        __nv_bfloat16 h[4], lo[4];
#pragma unroll
        for (int e = 0; e < 4; e++) split_bf16(ov[e], h[e], lo[e]);
        *(uint2*)(g_vh + o) = make_uint2(pack_bf2(h[0], h[1]),  pack_bf2(h[2], h[3]));
        *(uint2*)(g_vl + o) = make_uint2(pack_bf2(lo[0], lo[1]), pack_bf2(lo[2], lo[3]));
#pragma unroll
        for (int e = 0; e < 4; e++) split_bf16(l[1][e + 1], h[e], lo[e]);
        *(uint2*)(g_xh + o) = make_uint2(pack_bf2(h[0], h[1]),  pack_bf2(h[2], h[3]));
        *(uint2*)(g_xl + o) = make_uint2(pack_bf2(lo[0], lo[1]), pack_bf2(lo[2], lo[3]));
    }
}

// ---------------- kernel 2: per-(b,h) gram matrix, split over N ----------------
__global__ __launch_bounds__(64) void gram_kernel()
{
    __shared__ __align__(16) float qs[GTILE][36];
    __shared__ __align__(16) float ks[GTILE][36];

    int bh = blockIdx.x;
    int sp = blockIdx.y;
    const int nlen = NPIX / NSPLIT;
    int n0 = sp * nlen;

    const float* qp = g_q + (size_t)bh * NCH * NPIX;
    const float* kp = g_k + (size_t)bh * NCH * NPIX;

    int tid = threadIdx.x;
    int tr = tid >> 3;
    int tc = tid & 7;

    float acc[4][4] = {};

    for (int t0 = n0; t0 < n0 + nlen; t0 += GTILE) {
        for (int l = tid; l < GTILE * NCH; l += 64) {
            int cc = l >> 6;
            int nn = l & 63;
            qs[nn][cc] = qp[(size_t)cc * NPIX + t0 + nn];
            ks[nn][cc] = kp[(size_t)cc * NPIX + t0 + nn];
        }
        __syncthreads();
#pragma unroll 4
        for (int nn = 0; nn < GTILE; nn++) {
            float4 qa = *(const float4*)&qs[nn][tr * 4];
            float4 kb = *(const float4*)&ks[nn][tc * 4];
            float qv[4] = {qa.x, qa.y, qa.z, qa.w};
            float kv[4] = {kb.x, kb.y, kb.z, kb.w};
#pragma unroll
            for (int i = 0; i < 4; i++)
#pragma unroll
                for (int j = 0; j < 4; j++)
                    acc[i][j] = fmaf(qv[i], kv[j], acc[i][j]);
        }
        __syncthreads();
    }

    float* pp = g_partial + ((size_t)sp * NB * NHEADS + bh) * NCH * NCH;
#pragma unroll
    for (int i = 0; i < 4; i++)
#pragma unroll
        for (int j = 0; j < 4; j++)
            pp[(tr * 4 + i) * NCH + (tc * 4 + j)] = acc[i][j];
}

// ---------------- kernel 3: reduce + softmax ----------------
__global__ __launch_bounds__(32) void softmax_kernel(const float* __restrict__ temperature)
{
    int bh = blockIdx.x;
    int h = bh & (NHEADS - 1);
    int c = threadIdx.x;
    float t = temperature[h];

    float vals[NCH];
#pragma unroll
    for (int d = 0; d < NCH; d++) {
        float s = 0.f;
        for (int sp = 0; sp < NSPLIT; sp++)
            s += g_partial[(((size_t)sp * NB * NHEADS + bh) * NCH + c) * NCH + d];
        vals[d] = s * t;
    }
    float mx = vals[0];
#pragma unroll
    for (int d = 1; d < NCH; d++) mx = fmaxf(mx, vals[d]);
    float sum = 0.f;
#pragma unroll
    for (int d = 0; d < NCH; d++) { vals[d] = __expf(vals[d] - mx); sum += vals[d]; }
    float inv = 1.f / sum;
    float* row = g_attn + ((size_t)bh * NCH + c) * NCH;
#pragma unroll
    for (int d = 0; d < NCH; d++) row[d] = vals[d] * inv;
}

// ---------------- kernel P1: W_eff (32x32 tiles, 64 blocks) + b_eff ----------------
__global__ __launch_bounds__(256) void weff_kernel(
    const float* __restrict__ fusion_w, const float* __restrict__ out_w,
    const float* __restrict__ out_b, const float* __restrict__ fusion_b,
    const float* __restrict__ gamma)
{
    __shared__ float Fs[32][33];
    __shared__ float Os[32][33];

    int f0 = (blockIdx.x >> 3) * 32;
    int c0 = (blockIdx.x & 7) * 32;
    int tid = threadIdx.x;
    int tx = tid & 15, ty = tid >> 4;

    if ((blockIdx.x & 7) == 0 && tid < 32) {
        int f = f0 + tid;
        float sb = 0.f;
        for (int o = 0; o < NC; o++)
            sb = fmaf(fusion_w[f * 2 * NC + o], out_b[o], sb);
        g_beff[f] = gamma[0] * sb + fusion_b[f];
    }

    float acc[2][2] = {};

    for (int ko = 0; ko < NC; ko += 32) {
#pragma unroll
        for (int r = 0; r < 4; r++) {
            int id = tid + r * 256;
            int ff = id >> 5, kk = id & 31;
            Fs[kk][ff] = fusion_w[(f0 + ff) * (2 * NC) + ko + kk];
            int kk2 = id >> 5, cc = id & 31;
            Os[kk2][cc] = out_w[(ko + kk2) * NC + c0 + cc];
        }
        __syncthreads();
#pragma unroll
        for (int k = 0; k < 32; k++) {
            float fv0 = Fs[k][ty * 2], fv1 = Fs[k][ty * 2 + 1];
            float ov0 = Os[k][tx * 2], ov1 = Os[k][tx * 2 + 1];
            acc[0][0] = fmaf(fv0, ov0, acc[0][0]);
            acc[0][1] = fmaf(fv0, ov1, acc[0][1]);
            acc[1][0] = fmaf(fv1, ov0, acc[1][0]);
            acc[1][1] = fmaf(fv1, ov1, acc[1][1]);
        }
        __syncthreads();
    }
    float g = gamma[0];
#pragma unroll
    for (int i = 0; i < 2; i++)
#pragma unroll
        for (int j = 0; j < 2; j++)
            g_weff[(f0 + ty * 2 + i) * NC + c0 + tx * 2 + j] = g * acc[i][j];
}

// ---------------- kernel P2: A_full -> pre-split bf16 ----------------
__global__ __launch_bounds__(512) void afull_kernel(const float* __restrict__ fusion_w)
{
    int bf = blockIdx.x;
    int b = bf >> 8, f = bf & 255;
    int col = threadIdx.x;
    float v;
    if (col < NC) {
        int h = col >> 5, d = col & 31;
        const float* wrow = g_weff + f * NC + h * NCH;
        const float* arow = g_attn + ((size_t)(b * NHEADS + h) * NCH) * NCH + d;
        float s = 0.f;
#pragma unroll
        for (int cc = 0; cc < NCH; cc++)
            s = fmaf(wrow[cc], arow[cc * NCH], s);
        v = s;
    } else {
        v = fusion_w[f * 2 * NC + col];
    }
    __nv_bfloat16 hi, lo;
    split_bf16(v, hi, lo);
    g_ah[(size_t)bf * 2 * NC + col] = hi;
    g_al[(size_t)bf * 2 * NC + col] = lo;
}

// ---------------- kernel 4: main GEMM — bf16 HMMA, cp.async 2-stage, BK=32 ----------------
// Y[b](256x16384) = A(256x512) @ [v; x](512x16384) + b_eff
// BM=128, BN=128, BK=32, 256 threads = 8 warps (2m x 4n), warp tile 64x32.
// Product sweeps de-interleaved: all 16 accs touched once per sweep (no HMMA RAW).
#define AP 40     // A smem pitch (bf16): 80B rows -> conflict-free ldmatrix
#define BP 136    // B smem pitch (bf16): 272B rows -> conflict-free ldmatrix.trans
__global__ __launch_bounds__(256, 2) void main_gemm(float* __restrict__ y)
{
    __shared__ __align__(128) __nv_bfloat16 As[2][2][128][AP];
    __shared__ __align__(128) __nv_bfloat16 Bs[2][2][32][BP];

    int b  = blockIdx.z;
    int m0 = blockIdx.y * 128;
    int n0 = blockIdx.x * 128;
    int tid  = threadIdx.x;
    int lane = tid & 31;
    int warp = tid >> 5;
    int wm = (warp >> 2) * 64;
    int wn = (warp & 3) * 32;
    int g = lane >> 2;
    int t = lane & 3;

    int lr = lane & 15;          // ldmatrix row within 16
    int lc = (lane >> 4) * 8;    // ldmatrix 8-col group

    const __nv_bfloat16* gA[2] = { g_ah + (size_t)(b * NC + m0) * (2 * NC),
                                   g_al + (size_t)(b * NC + m0) * (2 * NC) };

    float acc[4][4][4];
#pragma unroll
    for (int i = 0; i < 4; i++)
#pragma unroll
        for (int j = 0; j < 4; j++)
#pragma unroll
            for (int r = 0; r < 4; r++) acc[i][j][r] = 0.f;

    auto load_stage = [&](int s, int it) {
        int k0 = it * 32;
#pragma unroll
        for (int c = 0; c < 4; c++) {
            int id = tid + c * 256;
            int half = id >> 9;
            int rem = id & 511;
            int row = rem >> 2;
            int kc = (rem & 3) * 8;
            cpa16(&As[s][half][row][kc], gA[half] + (size_t)row * (2 * NC) + k0 + kc);
        }
#pragma unroll
        for (int c = 0; c < 4; c++) {
            int id = tid + c * 256;
            int half = id >> 9;
            int rem = id & 511;
            int krow = rem >> 4;
            int nc = (rem & 15) * 8;
            int grow = k0 + krow;
            const __nv_bfloat16* src;
            if (grow < NC)
                src = (half ? g_vl : g_vh) + (size_t)(b * NC + grow) * NPIX + n0 + nc;
            else
                src = (half ? g_xl : g_xh) + (size_t)(b * NC + grow - NC) * NPIX + n0 + nc;
            cpa16(&Bs[s][half][krow][nc], src);
        }
        asm volatile("cp.async.commit_group;");
    };

    load_stage(0, 0);

    const int NIT = (2 * NC) / 32;   // 16
    for (int it = 0; it < NIT; it++) {
        int cur = it & 1;
        if (it + 1 < NIT) {
            load_stage(cur ^ 1, it + 1);
            asm volatile("cp.async.wait_group 1;");
        } else {
            asm volatile("cp.async.wait_group 0;");
        }
        __syncthreads();

#pragma unroll
        for (int ks = 0; ks < 2; ks++) {
            int kof = ks * 16;
            // B fragments (hi and lo)
            unsigned bh[4][2], bl[4][2];
#pragma unroll
            for (int nb = 0; nb < 2; nb++) {
                unsigned d0, d1, d2, d3;
                ldsm4t(d0, d1, d2, d3, &Bs[cur][0][kof + lr][wn + nb * 16 + lc]);
                bh[nb * 2][0] = d0; bh[nb * 2][1] = d1;
                bh[nb * 2 + 1][0] = d2; bh[nb * 2 + 1][1] = d3;
                ldsm4t(d0, d1, d2, d3, &Bs[cur][1][kof + lr][wn + nb * 16 + lc]);
                bl[nb * 2][0] = d0; bl[nb * 2][1] = d1;
                bl[nb * 2 + 1][0] = d2; bl[nb * 2 + 1][1] = d3;
            }
            // A-hi fragments
            unsigned af[4][4];
#pragma unroll
            for (int mf = 0; mf < 4; mf++)
                ldsm4(af[mf][0], af[mf][1], af[mf][2], af[mf][3],
                      &As[cur][0][wm + mf * 16 + lr][kof + lc]);
            // sweep 1: Ah * Bh  (16 distinct accs, no RAW)
#pragma unroll
            for (int nf = 0; nf < 4; nf++)
#pragma unroll
                for (int mf = 0; mf < 4; mf++)
                    mma_bf16(acc[mf][nf], af[mf], bh[nf]);
            // sweep 2: Ah * Bl
#pragma unroll
            for (int nf = 0; nf < 4; nf++)
#pragma unroll
                for (int mf = 0; mf < 4; mf++)
                    mma_bf16(acc[mf][nf], af[mf], bl[nf]);
            // A-lo fragments (reuse regs)
#pragma unroll
            for (int mf = 0; mf < 4; mf++)
                ldsm4(af[mf][0], af[mf][1], af[mf][2], af[mf][3],
                      &As[cur][1][wm + mf * 16 + lr][kof + lc]);
            // sweep 3: Al * Bh
#pragma unroll
            for (int nf = 0; nf < 4; nf++)
#pragma unroll
                for (int mf = 0; mf < 4; mf++)
                    mma_bf16(acc[mf][nf], af[mf], bh[nf]);
        }
        __syncthreads();
    }

    // epilogue
#pragma unroll
    for (int mf = 0; mf < 4; mf++) {
        int m = m0 + wm + mf * 16 + g;
        float be0 = g_beff[m];
        float be1 = g_beff[m + 8];
        float* yr0 = y + (size_t)(b * NC + m) * NPIX + n0 + wn;
        float* yr1 = yr0 + (size_t)8 * NPIX;
#pragma unroll
        for (int nf = 0; nf < 4; nf++) {
            *(float2*)(yr0 + nf * 8 + t * 2) =
                make_float2(acc[mf][nf][0] + be0, acc[mf][nf][1] + be0);
            *(float2*)(yr1 + nf * 8 + t * 2) =
                make_float2(acc[mf][nf][2] + be1, acc[mf][nf][3] + be1);
        }
    }
}

// ---------------- launch ----------------
extern "C" void kernel_launch(void* const* d_in, const int* in_sizes, int n_in,
                              void* d_out, int out_size)
{
    const float* x        = (const float*)d_in[0];
    const float* q_w      = (const float*)d_in[1];
    const float* q_b      = (const float*)d_in[2];
    const float* k_w      = (const float*)d_in[3];
    const float* k_b      = (const float*)d_in[4];
    const float* v_w      = (const float*)d_in[5];
    const float* v_b      = (const float*)d_in[6];
    const float* out_w    = (const float*)d_in[7];
    const float* out_b    = (const float*)d_in[8];
    const float* fusion_w = (const float*)d_in[9];
    const float* fusion_b = (const float*)d_in[10];
    const float* temperature = (const float*)d_in[11];
    const float* gamma    = (const float*)d_in[12];
    float* y = (float*)d_out;

    dwconv_qkv<<<NB * NC, 256>>>(x, q_w, q_b, k_w, k_b, v_w, v_b);

    dim3 ggrid(NB * NHEADS, NSPLIT);
    gram_kernel<<<ggrid, 64>>>();

    softmax_kernel<<<NB * NHEADS, NCH>>>(temperature);

    weff_kernel<<<64, 256>>>(fusion_w, out_w, out_b, fusion_b, gamma);
    afull_kernel<<<NB * NC, 2 * NC>>>(fusion_w);

    dim3 mgrid(NPIX / 128, NC / 128, NB);
    main_gemm<<<mgrid, 256>>>(y);
}